// round 1
// baseline (speedup 1.0000x reference)
#include <cuda_runtime.h>
#include <math.h>

#define B_  8
#define T_  4096
#define C_  512
#define U_  512
#define NG  1536    // 3*U
#define K_  1024    // 2*C
#define S_  16      // scan chunks
#define CH_ 256     // chunk length (S_*CH_ == T_)

// Scratch (device globals: allocation-free rule)
__device__ float g_pad[B_ * (T_ + 1) * C_];     // padded inputs, zero row at t=T
__device__ float g_gates[(size_t)B_ * T_ * NG]; // activated gates: tanh(x), sig(f), sig(o)
__device__ float g_cend[B_ * S_ * U_];
__device__ float g_fprod[B_ * S_ * U_];
__device__ float g_carry[B_ * S_ * U_];

// ---------------------------------------------------------------------------
// Pad copy: g_pad[b][t][c] = inputs[b][t][c], zero at t == T
// ---------------------------------------------------------------------------
__global__ void pad_copy(const float* __restrict__ in) {
    int idx = blockIdx.x * blockDim.x + threadIdx.x;
    const int per_b = (T_ + 1) * C_;
    if (idx >= B_ * per_b) return;
    int b = idx / per_b;
    int r = idx - b * per_b;
    int t = r / C_;
    int c = r - t * C_;
    g_pad[idx] = (t < T_) ? in[((size_t)(b * T_ + t)) * C_ + c] : 0.0f;
}

// ---------------------------------------------------------------------------
// GEMM + activation epilogue.
// A: g_pad, per M-tile base (b*(T+1)+t0)*C, rows stride C_=512, window length K_=1024
// B: W [1024 x 1536] row-major (the conv kernel reinterpreted)
// out: g_gates[m][n] = act(A@W + bias)
// ---------------------------------------------------------------------------
__global__ __launch_bounds__(256) void gemm_act(const float* __restrict__ W,
                                                const float* __restrict__ bias) {
    __shared__ float As[16][128];
    __shared__ float Bs[16][128];

    const int bn  = blockIdx.x;       // N tile (12)
    const int bm  = blockIdx.y;       // M tile (256)
    const int tid = threadIdx.x;

    const int gm0 = bm * 128;
    const int b   = gm0 >> 12;        // T_=4096 rows per batch
    const int t0  = gm0 & (T_ - 1);
    const float* Abase = g_pad + ((size_t)(b * (T_ + 1) + t0)) * C_;
    const int n0 = bn * 128;

    const int trow = tid >> 4;        // 0..15
    const int tcol = tid & 15;        // 0..15

    float acc[8][8];
#pragma unroll
    for (int i = 0; i < 8; i++)
#pragma unroll
        for (int j = 0; j < 8; j++) acc[i][j] = 0.0f;

    for (int kk = 0; kk < K_; kk += 16) {
        // Load A tile: 128 rows x 16 k  (512 float4, 2 per thread), transpose to As[k][m]
#pragma unroll
        for (int l = 0; l < 2; l++) {
            int id = tid + l * 256;
            int r  = id >> 2;
            int kq = (id & 3) * 4;
            float4 v = *(const float4*)(Abase + (size_t)r * C_ + kk + kq);
            As[kq + 0][r] = v.x;
            As[kq + 1][r] = v.y;
            As[kq + 2][r] = v.z;
            As[kq + 3][r] = v.w;
        }
        // Load B tile: 16 k x 128 n (512 float4, 2 per thread)
#pragma unroll
        for (int l = 0; l < 2; l++) {
            int id = tid + l * 256;
            int k  = id >> 5;
            int nq = (id & 31) * 4;
            *(float4*)&Bs[k][nq] =
                *(const float4*)(W + (size_t)(kk + k) * NG + n0 + nq);
        }
        __syncthreads();

#pragma unroll
        for (int k = 0; k < 16; k++) {
            float a[8], bb[8];
            *(float4*)(a)      = *(float4*)&As[k][trow * 8];
            *(float4*)(a + 4)  = *(float4*)&As[k][trow * 8 + 4];
            *(float4*)(bb)     = *(float4*)&Bs[k][tcol * 8];
            *(float4*)(bb + 4) = *(float4*)&Bs[k][tcol * 8 + 4];
#pragma unroll
            for (int i = 0; i < 8; i++)
#pragma unroll
                for (int j = 0; j < 8; j++) acc[i][j] += a[i] * bb[j];
        }
        __syncthreads();
    }

    // Epilogue: bias + activation, write to g_gates
    const int gn0 = n0 + tcol * 8;
#pragma unroll
    for (int i = 0; i < 8; i++) {
        int gm = gm0 + trow * 8 + i;
        float* orow = g_gates + (size_t)gm * NG;
#pragma unroll
        for (int j = 0; j < 8; j++) {
            int   n = gn0 + j;
            float v = acc[i][j] + bias[n];
            if (n < U_)
                v = tanhf(v);                    // x gate
            else
                v = 1.0f / (1.0f + expf(-v));    // f / o gates
            orow[n] = v;
        }
    }
}

// ---------------------------------------------------------------------------
// Scan pass A: per (b, chunk s, u) compute local c_end (from c=0) and F = prod f
// ---------------------------------------------------------------------------
__global__ void scan_partial() {
    int u = blockIdx.x * blockDim.x + threadIdx.x;  // 0..511
    int s = blockIdx.y;
    int b = blockIdx.z;
    const float* gp = g_gates + ((size_t)(b * T_ + s * CH_)) * NG;
    float c = 0.0f, F = 1.0f;
    for (int t = 0; t < CH_; t++) {
        float x = gp[(size_t)t * NG + u];
        float f = gp[(size_t)t * NG + U_ + u];
        c = fmaf(f, c - x, x);   // f*c + (1-f)*x
        F *= f;
    }
    int off = (b * S_ + s) * U_ + u;
    g_cend[off]  = c;
    g_fprod[off] = F;
}

// ---------------------------------------------------------------------------
// Scan pass B: sequential combine over the S_ chunk summaries per (b,u),
// storing the carry ENTERING each chunk.
// ---------------------------------------------------------------------------
__global__ void scan_carry() {
    int idx = blockIdx.x * blockDim.x + threadIdx.x;   // B_*U_ = 4096
    if (idx >= B_ * U_) return;
    int b = idx >> 9;
    int u = idx & (U_ - 1);
    float c = 0.0f;
    for (int s = 0; s < S_; s++) {
        int off = (b * S_ + s) * U_ + u;
        g_carry[off] = c;
        c = fmaf(g_fprod[off], c, g_cend[off]);
    }
}

// ---------------------------------------------------------------------------
// Scan pass C: replay each chunk from its true carry, apply output gate.
// ---------------------------------------------------------------------------
__global__ void scan_final(float* __restrict__ out) {
    int u = blockIdx.x * blockDim.x + threadIdx.x;
    int s = blockIdx.y;
    int b = blockIdx.z;
    const float* gp = g_gates + ((size_t)(b * T_ + s * CH_)) * NG;
    float* op = out + ((size_t)(b * T_ + s * CH_)) * U_;
    float c = g_carry[(b * S_ + s) * U_ + u];
    for (int t = 0; t < CH_; t++) {
        float x = gp[(size_t)t * NG + u];
        float f = gp[(size_t)t * NG + U_ + u];
        float o = gp[(size_t)t * NG + 2 * U_ + u];
        c = fmaf(f, c - x, x);
        op[(size_t)t * U_ + u] = o * c;
    }
}

// ---------------------------------------------------------------------------
extern "C" void kernel_launch(void* const* d_in, const int* in_sizes, int n_in,
                              void* d_out, int out_size) {
    const float* in   = (const float*)d_in[0];
    const float* W    = (const float*)d_in[1];
    const float* bias = (const float*)d_in[2];
    float* out = (float*)d_out;

    int npad = B_ * (T_ + 1) * C_;
    pad_copy<<<(npad + 255) / 256, 256>>>(in);

    dim3 gGemm(NG / 128, (B_ * T_) / 128);   // (12, 256)
    gemm_act<<<gGemm, 256>>>(W, bias);

    dim3 gScan(U_ / 256, S_, B_);            // (2, 16, 8)
    scan_partial<<<gScan, 256>>>();
    scan_carry<<<(B_ * U_ + 255) / 256, 256>>>();
    scan_final<<<gScan, 256>>>(out);
}

// round 4
// speedup vs baseline: 1.8095x; 1.8095x over previous
#include <cuda_runtime.h>
#include <cuda_bf16.h>
#include <math.h>
#include <stdint.h>

#define B_  8
#define T_  4096
#define C_  512
#define U_  512
#define NG  1536            // 3*U
#define K_  1024            // 2*C
#define S_  16              // scan chunks
#define CH_ 256             // chunk length
#define TP_ 4097            // padded rows per batch (zero row at t=T)

#define BM  128
#define BN  128
#define BK  32
#define NKITER 96           // 3 products * (K_/BK)
#define NSTAGE 4
#define STAGE_BYTES 16384   // 8KB A + 8KB B
#define SMEM_TOTAL (NSTAGE * STAGE_BYTES)

// ---- device scratch (allocation-free rule) --------------------------------
__device__ __align__(128) __nv_bfloat16 g_a_hi[B_ * TP_ * C_];
__device__ __align__(128) __nv_bfloat16 g_a_lo[B_ * TP_ * C_];
__device__ __align__(128) __nv_bfloat16 g_b_hi[NG * K_];   // [n][k]
__device__ __align__(128) __nv_bfloat16 g_b_lo[NG * K_];
__device__ __align__(128) float g_gates[(size_t)B_ * T_ * NG];
__device__ float g_cend[B_ * S_ * U_];
__device__ float g_fprod[B_ * S_ * U_];
__device__ float g_carry[B_ * S_ * U_];

// ---------------------------------------------------------------------------
__device__ __forceinline__ uint32_t smem_u32(const void* p) {
    uint32_t a;
    asm("{ .reg .u64 t; cvta.to.shared.u64 t, %1; cvt.u32.u64 %0, t; }" : "=r"(a) : "l"(p));
    return a;
}
__device__ __forceinline__ void cp16(uint32_t saddr, const void* gaddr) {
    asm volatile("cp.async.cg.shared.global [%0], [%1], 16;" :: "r"(saddr), "l"(gaddr));
}
__device__ __forceinline__ void cp_commit() {
    asm volatile("cp.async.commit_group;" ::: "memory");
}
__device__ __forceinline__ void cp_wait2() {
    asm volatile("cp.async.wait_group 2;" ::: "memory");
}
__device__ __forceinline__ void ldm_x4(uint32_t* r, uint32_t addr) {
    asm volatile("ldmatrix.sync.aligned.m8n8.x4.shared.b16 {%0,%1,%2,%3}, [%4];"
                 : "=r"(r[0]), "=r"(r[1]), "=r"(r[2]), "=r"(r[3]) : "r"(addr));
}
__device__ __forceinline__ void mma_bf16(float* d, const uint32_t* a, uint32_t b0, uint32_t b1) {
    asm volatile(
        "mma.sync.aligned.m16n8k16.row.col.f32.bf16.bf16.f32 "
        "{%0,%1,%2,%3}, {%4,%5,%6,%7}, {%8,%9}, {%0,%1,%2,%3};"
        : "+f"(d[0]), "+f"(d[1]), "+f"(d[2]), "+f"(d[3])
        : "r"(a[0]), "r"(a[1]), "r"(a[2]), "r"(a[3]), "r"(b0), "r"(b1));
}

// ---------------------------------------------------------------------------
// Prep: fp32 -> bf16 hi/lo split
// ---------------------------------------------------------------------------
__global__ void prep_a(const float* __restrict__ in) {
    int idx = blockIdx.x * blockDim.x + threadIdx.x;
    if (idx >= B_ * TP_ * C_) return;
    int c = idx & (C_ - 1);
    int r = idx >> 9;
    int b = r / TP_;
    int t = r - b * TP_;
    float v = (t < T_) ? in[((size_t)(b * T_ + t)) * C_ + c] : 0.0f;
    __nv_bfloat16 hi = __float2bfloat16(v);
    __nv_bfloat16 lo = __float2bfloat16(v - __bfloat162float(hi));
    g_a_hi[idx] = hi;
    g_a_lo[idx] = lo;
}

__global__ void prep_w(const float* __restrict__ W) {
    int idx = blockIdx.x * blockDim.x + threadIdx.x;   // over K_*NG
    if (idx >= K_ * NG) return;
    int k = idx / NG;
    int n = idx - k * NG;
    float v = W[idx];
    __nv_bfloat16 hi = __float2bfloat16(v);
    __nv_bfloat16 lo = __float2bfloat16(v - __bfloat162float(hi));
    g_b_hi[(size_t)n * K_ + k] = hi;
    g_b_lo[(size_t)n * K_ + k] = lo;
}

// ---------------------------------------------------------------------------
// HMMA GEMM: gates = act(A @ W + bias)
// Extended-K (3072): p = kiter/32 selects (Ahi,Whi), (Ahi,Wlo), (Alo,Whi).
// grid (NG/BN=12, (B_*T_)/BM=256), 256 threads (8 warps, 2(M) x 4(N))
// ---------------------------------------------------------------------------
__global__ void __launch_bounds__(256) gemm_mma(const float* __restrict__ bias) {
    extern __shared__ char smem[];
    const uint32_t sb = smem_u32(smem);
    const int tid  = threadIdx.x;
    const int wid  = tid >> 5;
    const int lane = tid & 31;

    const int bn  = blockIdx.x, bm = blockIdx.y;
    const int gm0 = bm * BM;
    const int b   = gm0 >> 12;
    const int t0  = gm0 & (T_ - 1);
    const int row0 = b * TP_ + t0;     // padded-row base; window overrun lands in pad row
    const int n0  = bn * BN;

    // cp.async issue for k-iteration `ki` into stage (ki & 3)
    auto issue = [&](int ki) {
        const int p  = ki >> 5;
        const int kk = (ki & 31) * BK;
        const __nv_bfloat16* Ag = (p < 2) ? g_a_hi : g_a_lo;
        const __nv_bfloat16* Bg = (p == 1) ? g_b_lo : g_b_hi;
        const uint32_t As = sb + (ki & 3) * STAGE_BYTES;
        const uint32_t Bs = As + 8192;
#pragma unroll
        for (int j = 0; j < 2; j++) {
            int tt  = tid + j * 256;
            int row = tt >> 2;
            int ch  = tt & 3;
            uint32_t so = row * 64 + (((ch ^ (row & 3))) << 4);
            cp16(As + so, Ag + (size_t)(row0 + row) * C_ + kk + ch * 8);
            cp16(Bs + so, Bg + (size_t)(n0 + row) * K_ + kk + ch * 8);
        }
    };

    // Warp tile: 64(M) x 32(N)
    const int wm0 = (wid >> 2) * 64;
    const int wn0 = (wid & 3) * 32;

    float acc[4][4][4];
#pragma unroll
    for (int i = 0; i < 4; i++)
#pragma unroll
        for (int j = 0; j < 4; j++)
#pragma unroll
            for (int q = 0; q < 4; q++) acc[i][j][q] = 0.0f;

    // prologue: 3 stages in flight
    issue(0); cp_commit();
    issue(1); cp_commit();
    issue(2); cp_commit();

    for (int ki = 0; ki < NKITER; ki++) {
        cp_wait2();
        __syncthreads();
        if (ki + 3 < NKITER) issue(ki + 3);
        cp_commit();                      // unconditional: keeps group count uniform

        const uint32_t As = sb + (ki & 3) * STAGE_BYTES;
        const uint32_t Bs = As + 8192;

#pragma unroll
        for (int ks = 0; ks < 2; ks++) {
            uint32_t af[4][4];
#pragma unroll
            for (int mt = 0; mt < 4; mt++) {
                int row = wm0 + mt * 16 + (lane & 15);
                int ch  = ks * 2 + (lane >> 4);
                ldm_x4(af[mt], As + row * 64 + (((ch ^ (row & 3))) << 4));
            }
            uint32_t bf[2][4];
#pragma unroll
            for (int bt = 0; bt < 2; bt++) {
                int row = wn0 + bt * 16 + (lane & 15);
                int ch  = ks * 2 + (lane >> 4);
                ldm_x4(bf[bt], Bs + row * 64 + (((ch ^ (row & 3))) << 4));
            }
#pragma unroll
            for (int mt = 0; mt < 4; mt++)
#pragma unroll
                for (int nt = 0; nt < 4; nt++)
                    mma_bf16(acc[mt][nt], af[mt], bf[nt >> 1][nt & 1], bf[nt >> 1][2 + (nt & 1)]);
        }
        __syncthreads();
    }

    // Epilogue: bias + activation (uniform per CTA: n0 < U_ => tanh block)
    const bool is_tanh = (n0 < U_);
    const int grow = lane >> 2;
    const int gcol = (lane & 3) * 2;
#pragma unroll
    for (int mt = 0; mt < 4; mt++) {
#pragma unroll
        for (int nt = 0; nt < 4; nt++) {
            int n = n0 + wn0 + nt * 8 + gcol;
            float b0 = __ldg(bias + n);
            float b1 = __ldg(bias + n + 1);
#pragma unroll
            for (int h = 0; h < 2; h++) {        // h=0: rows 0-7, h=1: rows 8-15
                int m = gm0 + wm0 + mt * 16 + grow + h * 8;
                float v0 = acc[mt][nt][2 * h]     + b0;
                float v1 = acc[mt][nt][2 * h + 1] + b1;
                if (is_tanh) {
                    float e0 = __expf(2.0f * v0), e1 = __expf(2.0f * v1);
                    v0 = 1.0f - 2.0f / (e0 + 1.0f);
                    v1 = 1.0f - 2.0f / (e1 + 1.0f);
                } else {
                    v0 = 1.0f / (1.0f + __expf(-v0));
                    v1 = 1.0f / (1.0f + __expf(-v1));
                }
                *(float2*)(g_gates + (size_t)m * NG + n) = make_float2(v0, v1);
            }
        }
    }
}

// ---------------------------------------------------------------------------
// Scan passes
// ---------------------------------------------------------------------------
__global__ void scan_partial() {
    int u = blockIdx.x * blockDim.x + threadIdx.x;
    int s = blockIdx.y;
    int b = blockIdx.z;
    const float* gp = g_gates + ((size_t)(b * T_ + s * CH_)) * NG;
    float c = 0.0f, F = 1.0f;
    for (int t = 0; t < CH_; t++) {
        float x = gp[(size_t)t * NG + u];
        float f = gp[(size_t)t * NG + U_ + u];
        c = fmaf(f, c - x, x);
        F *= f;
    }
    int off = (b * S_ + s) * U_ + u;
    g_cend[off]  = c;
    g_fprod[off] = F;
}

__global__ void scan_carry() {
    int idx = blockIdx.x * blockDim.x + threadIdx.x;
    if (idx >= B_ * U_) return;
    int b = idx >> 9;
    int u = idx & (U_ - 1);
    float c = 0.0f;
    for (int s = 0; s < S_; s++) {
        int off = (b * S_ + s) * U_ + u;
        g_carry[off] = c;
        c = fmaf(g_fprod[off], c, g_cend[off]);
    }
}

__global__ void scan_final(float* __restrict__ out) {
    int u = blockIdx.x * blockDim.x + threadIdx.x;
    int s = blockIdx.y;
    int b = blockIdx.z;
    const float* gp = g_gates + ((size_t)(b * T_ + s * CH_)) * NG;
    float* op = out + ((size_t)(b * T_ + s * CH_)) * U_;
    float c = g_carry[(b * S_ + s) * U_ + u];
    for (int t = 0; t < CH_; t++) {
        float x = gp[(size_t)t * NG + u];
        float f = gp[(size_t)t * NG + U_ + u];
        float o = gp[(size_t)t * NG + 2 * U_ + u];
        c = fmaf(f, c - x, x);
        op[(size_t)t * U_ + u] = o * c;
    }
}

// ---------------------------------------------------------------------------
extern "C" void kernel_launch(void* const* d_in, const int* in_sizes, int n_in,
                              void* d_out, int out_size) {
    const float* in   = (const float*)d_in[0];
    const float* W    = (const float*)d_in[1];
    const float* bias = (const float*)d_in[2];
    float* out = (float*)d_out;

    int na = B_ * TP_ * C_;
    prep_a<<<(na + 255) / 256, 256>>>(in);
    prep_w<<<(K_ * NG + 255) / 256, 256>>>(W);

    cudaFuncSetAttribute(gemm_mma, cudaFuncAttributeMaxDynamicSharedMemorySize, SMEM_TOTAL);
    dim3 gGemm(NG / BN, (B_ * T_) / BM);   // (12, 256)
    gemm_mma<<<gGemm, 256, SMEM_TOTAL>>>(bias);

    dim3 gScan(U_ / 256, S_, B_);
    scan_partial<<<gScan, 256>>>();
    scan_carry<<<(B_ * U_ + 255) / 256, 256>>>();
    scan_final<<<gScan, 256>>>(out);
}

// round 5
// speedup vs baseline: 2.1671x; 1.1976x over previous
#include <cuda_runtime.h>
#include <cuda_bf16.h>
#include <math.h>
#include <stdint.h>

#define B_  8
#define T_  4096
#define C_  512
#define U_  512
#define NG  1536            // 3*U
#define K_  1024            // 2*C
#define S_  16              // scan chunks
#define CH_ 256             // chunk length
#define TP_ 4097            // padded rows per batch (zero row at t=T)

#define BM  128
#define BN  128
#define BK  32
#define NKK (K_ / BK)       // 32 k-slices
#define NSTAGE 3
#define STAGE_BYTES 32768   // Ahi 8K | Alo 8K | Whi 8K | Wlo 8K
#define SMEM_TOTAL (NSTAGE * STAGE_BYTES)

// ---- device scratch (allocation-free rule) --------------------------------
__device__ __align__(128) __nv_bfloat16 g_a_hi[B_ * TP_ * C_];
__device__ __align__(128) __nv_bfloat16 g_a_lo[B_ * TP_ * C_];
__device__ __align__(128) __nv_bfloat16 g_b_hi[NG * K_];   // [n][k]
__device__ __align__(128) __nv_bfloat16 g_b_lo[NG * K_];
__device__ __align__(128) float g_gates[(size_t)B_ * T_ * NG];
__device__ float g_cend[B_ * S_ * U_];
__device__ float g_fprod[B_ * S_ * U_];
__device__ float g_carry[B_ * S_ * U_];

// ---------------------------------------------------------------------------
__device__ __forceinline__ uint32_t smem_u32(const void* p) {
    uint32_t a;
    asm("{ .reg .u64 t; cvta.to.shared.u64 t, %1; cvt.u32.u64 %0, t; }" : "=r"(a) : "l"(p));
    return a;
}
__device__ __forceinline__ void cp16(uint32_t saddr, const void* gaddr) {
    asm volatile("cp.async.cg.shared.global [%0], [%1], 16;" :: "r"(saddr), "l"(gaddr));
}
__device__ __forceinline__ void cp_commit() {
    asm volatile("cp.async.commit_group;" ::: "memory");
}
__device__ __forceinline__ void cp_wait1() {
    asm volatile("cp.async.wait_group 1;" ::: "memory");
}
__device__ __forceinline__ void ldm_x4(uint32_t* r, uint32_t addr) {
    asm volatile("ldmatrix.sync.aligned.m8n8.x4.shared.b16 {%0,%1,%2,%3}, [%4];"
                 : "=r"(r[0]), "=r"(r[1]), "=r"(r[2]), "=r"(r[3]) : "r"(addr));
}
__device__ __forceinline__ void mma_bf16(float* d, const uint32_t* a, uint32_t b0, uint32_t b1) {
    asm volatile(
        "mma.sync.aligned.m16n8k16.row.col.f32.bf16.bf16.f32 "
        "{%0,%1,%2,%3}, {%4,%5,%6,%7}, {%8,%9}, {%0,%1,%2,%3};"
        : "+f"(d[0]), "+f"(d[1]), "+f"(d[2]), "+f"(d[3])
        : "r"(a[0]), "r"(a[1]), "r"(a[2]), "r"(a[3]), "r"(b0), "r"(b1));
}

// ---------------------------------------------------------------------------
// Prep: fp32 -> bf16 hi/lo split
// ---------------------------------------------------------------------------
__global__ void prep_a(const float* __restrict__ in) {
    int idx = blockIdx.x * blockDim.x + threadIdx.x;
    if (idx >= B_ * TP_ * C_) return;
    int c = idx & (C_ - 1);
    int r = idx >> 9;
    int b = r / TP_;
    int t = r - b * TP_;
    float v = (t < T_) ? in[((size_t)(b * T_ + t)) * C_ + c] : 0.0f;
    __nv_bfloat16 hi = __float2bfloat16(v);
    __nv_bfloat16 lo = __float2bfloat16(v - __bfloat162float(hi));
    g_a_hi[idx] = hi;
    g_a_lo[idx] = lo;
}

__global__ void prep_w(const float* __restrict__ W) {
    int idx = blockIdx.x * blockDim.x + threadIdx.x;   // over K_*NG
    if (idx >= K_ * NG) return;
    int k = idx / NG;
    int n = idx - k * NG;
    float v = W[idx];
    __nv_bfloat16 hi = __float2bfloat16(v);
    __nv_bfloat16 lo = __float2bfloat16(v - __bfloat162float(hi));
    g_b_hi[(size_t)n * K_ + k] = hi;
    g_b_lo[(size_t)n * K_ + k] = lo;
}

// ---------------------------------------------------------------------------
// HMMA GEMM with hi/lo tile reuse: per k-slice load Ahi,Alo,Whi,Wlo once,
// issue 3 products (Ahi*Whi, Ahi*Wlo, Alo*Whi). Single barrier per slice.
// grid (NG/BN=12, (B_*T_)/BM=256), 256 threads (8 warps, 2(M) x 4(N))
// ---------------------------------------------------------------------------
__global__ void __launch_bounds__(256) gemm_mma(const float* __restrict__ bias) {
    extern __shared__ char smem[];
    const uint32_t sb = smem_u32(smem);
    const int tid  = threadIdx.x;
    const int wid  = tid >> 5;
    const int lane = tid & 31;

    const int bn  = blockIdx.x, bm = blockIdx.y;
    const int gm0 = bm * BM;
    const int b   = gm0 >> 12;
    const int t0  = gm0 & (T_ - 1);
    const int row0 = b * TP_ + t0;     // padded-row base; window overrun lands in pad row
    const int n0  = bn * BN;

    // per-thread static load coords (2 row/chunk pairs covering 128x32 tile)
    const int r0l = tid >> 2,        c0l = tid & 3;
    const int r1l = (tid + 256) >> 2, c1l = (tid + 256) & 3;
    const uint32_t so0 = r0l * 64 + ((c0l ^ (r0l & 3)) << 4);
    const uint32_t so1 = r1l * 64 + ((c1l ^ (r1l & 3)) << 4);

    auto issue = [&](int kk) {
        const uint32_t st = sb + (kk % NSTAGE) * STAGE_BYTES;
        const int kb = kk * BK;
        const __nv_bfloat16* a0 = g_a_hi + (size_t)(row0 + r0l) * C_ + kb + c0l * 8;
        const __nv_bfloat16* a1 = g_a_hi + (size_t)(row0 + r1l) * C_ + kb + c1l * 8;
        const __nv_bfloat16* w0 = g_b_hi + (size_t)(n0 + r0l) * K_ + kb + c0l * 8;
        const __nv_bfloat16* w1 = g_b_hi + (size_t)(n0 + r1l) * K_ + kb + c1l * 8;
        const ptrdiff_t dA = g_a_lo - g_a_hi;
        const ptrdiff_t dW = g_b_lo - g_b_hi;
        cp16(st + so0,          a0);
        cp16(st + so1,          a1);
        cp16(st + 8192  + so0,  a0 + dA);
        cp16(st + 8192  + so1,  a1 + dA);
        cp16(st + 16384 + so0,  w0);
        cp16(st + 16384 + so1,  w1);
        cp16(st + 24576 + so0,  w0 + dW);
        cp16(st + 24576 + so1,  w1 + dW);
    };

    // Warp tile: 64(M) x 32(N)
    const int wm0 = (wid >> 2) * 64;
    const int wn0 = (wid & 3) * 32;

    float acc[4][4][4];
#pragma unroll
    for (int i = 0; i < 4; i++)
#pragma unroll
        for (int j = 0; j < 4; j++)
#pragma unroll
            for (int q = 0; q < 4; q++) acc[i][j][q] = 0.0f;

    issue(0); cp_commit();
    issue(1); cp_commit();

    for (int kk = 0; kk < NKK; kk++) {
        cp_wait1();
        __syncthreads();
        if (kk + 2 < NKK) issue(kk + 2);
        cp_commit();                      // uniform group count

        const uint32_t st  = sb + (kk % NSTAGE) * STAGE_BYTES;
        const uint32_t Ahs = st, Als = st + 8192, Whs = st + 16384, Wls = st + 24576;

#pragma unroll
        for (int ks = 0; ks < 2; ks++) {
            const int ch = ks * 2 + (lane >> 4);
            uint32_t ah[4][4], al[4][4], wh[2][4], wl[2][4];
#pragma unroll
            for (int mt = 0; mt < 4; mt++) {
                int row = wm0 + mt * 16 + (lane & 15);
                uint32_t off = row * 64 + ((ch ^ (row & 3)) << 4);
                ldm_x4(ah[mt], Ahs + off);
                ldm_x4(al[mt], Als + off);
            }
#pragma unroll
            for (int bt = 0; bt < 2; bt++) {
                int row = wn0 + bt * 16 + (lane & 15);
                uint32_t off = row * 64 + ((ch ^ (row & 3)) << 4);
                ldm_x4(wh[bt], Whs + off);
                ldm_x4(wl[bt], Wls + off);
            }
            // product 1: Ahi * Whi
#pragma unroll
            for (int mt = 0; mt < 4; mt++)
#pragma unroll
                for (int nt = 0; nt < 4; nt++)
                    mma_bf16(acc[mt][nt], ah[mt], wh[nt >> 1][nt & 1], wh[nt >> 1][2 + (nt & 1)]);
            // product 2: Ahi * Wlo
#pragma unroll
            for (int mt = 0; mt < 4; mt++)
#pragma unroll
                for (int nt = 0; nt < 4; nt++)
                    mma_bf16(acc[mt][nt], ah[mt], wl[nt >> 1][nt & 1], wl[nt >> 1][2 + (nt & 1)]);
            // product 3: Alo * Whi
#pragma unroll
            for (int mt = 0; mt < 4; mt++)
#pragma unroll
                for (int nt = 0; nt < 4; nt++)
                    mma_bf16(acc[mt][nt], al[mt], wh[nt >> 1][nt & 1], wh[nt >> 1][2 + (nt & 1)]);
        }
    }

    // Epilogue: bias + activation (uniform per CTA: n0 < U_ => tanh block)
    const bool is_tanh = (n0 < U_);
    const int grow = lane >> 2;
    const int gcol = (lane & 3) * 2;
#pragma unroll
    for (int mt = 0; mt < 4; mt++) {
#pragma unroll
        for (int nt = 0; nt < 4; nt++) {
            int n = n0 + wn0 + nt * 8 + gcol;
            float b0 = __ldg(bias + n);
            float b1 = __ldg(bias + n + 1);
#pragma unroll
            for (int h = 0; h < 2; h++) {
                int m = gm0 + wm0 + mt * 16 + grow + h * 8;
                float v0 = acc[mt][nt][2 * h]     + b0;
                float v1 = acc[mt][nt][2 * h + 1] + b1;
                if (is_tanh) {
                    float e0 = __expf(2.0f * v0), e1 = __expf(2.0f * v1);
                    v0 = 1.0f - 2.0f / (e0 + 1.0f);
                    v1 = 1.0f - 2.0f / (e1 + 1.0f);
                } else {
                    v0 = 1.0f / (1.0f + __expf(-v0));
                    v1 = 1.0f / (1.0f + __expf(-v1));
                }
                *(float2*)(g_gates + (size_t)m * NG + n) = make_float2(v0, v1);
            }
        }
    }
}

// ---------------------------------------------------------------------------
// Scan passes (float2-widened)
// ---------------------------------------------------------------------------
__global__ void scan_partial() {
    int u = (blockIdx.x * blockDim.x + threadIdx.x) * 2;   // 256 threads cover 512 u
    int s = blockIdx.y;
    int b = blockIdx.z;
    const float* gp = g_gates + ((size_t)(b * T_ + s * CH_)) * NG;
    float2 c = make_float2(0.f, 0.f), F = make_float2(1.f, 1.f);
    for (int t = 0; t < CH_; t++) {
        float2 x = *(const float2*)(gp + (size_t)t * NG + u);
        float2 f = *(const float2*)(gp + (size_t)t * NG + U_ + u);
        c.x = fmaf(f.x, c.x - x.x, x.x);
        c.y = fmaf(f.y, c.y - x.y, x.y);
        F.x *= f.x; F.y *= f.y;
    }
    int off = (b * S_ + s) * U_ + u;
    *(float2*)(g_cend  + off) = c;
    *(float2*)(g_fprod + off) = F;
}

__global__ void scan_carry() {
    int idx = blockIdx.x * blockDim.x + threadIdx.x;
    if (idx >= B_ * U_) return;
    int b = idx >> 9;
    int u = idx & (U_ - 1);
    float c = 0.0f;
    for (int s = 0; s < S_; s++) {
        int off = (b * S_ + s) * U_ + u;
        g_carry[off] = c;
        c = fmaf(g_fprod[off], c, g_cend[off]);
    }
}

__global__ void scan_final(float* __restrict__ out) {
    int u = (blockIdx.x * blockDim.x + threadIdx.x) * 2;
    int s = blockIdx.y;
    int b = blockIdx.z;
    const float* gp = g_gates + ((size_t)(b * T_ + s * CH_)) * NG;
    float* op = out + ((size_t)(b * T_ + s * CH_)) * U_;
    float2 c = *(const float2*)(g_carry + (b * S_ + s) * U_ + u);
    for (int t = 0; t < CH_; t++) {
        float2 x = *(const float2*)(gp + (size_t)t * NG + u);
        float2 f = *(const float2*)(gp + (size_t)t * NG + U_ + u);
        float2 o = *(const float2*)(gp + (size_t)t * NG + 2 * U_ + u);
        c.x = fmaf(f.x, c.x - x.x, x.x);
        c.y = fmaf(f.y, c.y - x.y, x.y);
        *(float2*)(op + (size_t)t * U_ + u) = make_float2(o.x * c.x, o.y * c.y);
    }
}

// ---------------------------------------------------------------------------
extern "C" void kernel_launch(void* const* d_in, const int* in_sizes, int n_in,
                              void* d_out, int out_size) {
    const float* in   = (const float*)d_in[0];
    const float* W    = (const float*)d_in[1];
    const float* bias = (const float*)d_in[2];
    float* out = (float*)d_out;

    int na = B_ * TP_ * C_;
    prep_a<<<(na + 255) / 256, 256>>>(in);
    prep_w<<<(K_ * NG + 255) / 256, 256>>>(W);

    cudaFuncSetAttribute(gemm_mma, cudaFuncAttributeMaxDynamicSharedMemorySize, SMEM_TOTAL);
    dim3 gGemm(NG / BN, (B_ * T_) / BM);   // (12, 256)
    gemm_mma<<<gGemm, 256, SMEM_TOTAL>>>(bias);

    dim3 gScan(1, S_, B_);
    scan_partial<<<gScan, 256>>>();
    scan_carry<<<(B_ * U_ + 255) / 256, 256>>>();
    scan_final<<<gScan, 256>>>(out);
}

// round 6
// speedup vs baseline: 2.8432x; 1.3120x over previous
#include <cuda_runtime.h>
#include <cuda_fp16.h>
#include <math.h>
#include <stdint.h>

#define B_  8
#define T_  4096
#define C_  512
#define U_  512
#define NG  1536            // 3*U
#define K_  1024            // 2*C
#define S_  16              // scan chunks
#define CH_ 256             // chunk length
#define TP_ 4097            // padded rows per batch (zero row at t=T)

#define BM  128
#define BN  128
#define BK  32
#define NKK (K_ / BK)       // 32 k-slices
#define NSTAGE 4
#define STAGE_BYTES 24576   // A 8K | Wh 8K | Wl 8K
#define SMEM_TOTAL (NSTAGE * STAGE_BYTES)

// ---- device scratch (allocation-free rule) --------------------------------
__device__ __align__(128) __half g_a16[B_ * TP_ * C_];
__device__ __align__(128) __half g_w_hi[NG * K_];   // [n][k]
__device__ __align__(128) __half g_w_lo[NG * K_];
__device__ __align__(128) float g_gates[(size_t)B_ * T_ * NG];
__device__ float g_cend[B_ * S_ * U_];
__device__ float g_fprod[B_ * S_ * U_];
__device__ float g_carry[B_ * S_ * U_];

// ---------------------------------------------------------------------------
__device__ __forceinline__ uint32_t smem_u32(const void* p) {
    uint32_t a;
    asm("{ .reg .u64 t; cvta.to.shared.u64 t, %1; cvt.u32.u64 %0, t; }" : "=r"(a) : "l"(p));
    return a;
}
__device__ __forceinline__ void cp16(uint32_t saddr, const void* gaddr) {
    asm volatile("cp.async.cg.shared.global [%0], [%1], 16;" :: "r"(saddr), "l"(gaddr));
}
__device__ __forceinline__ void cp_commit() {
    asm volatile("cp.async.commit_group;" ::: "memory");
}
__device__ __forceinline__ void cp_wait2() {
    asm volatile("cp.async.wait_group 2;" ::: "memory");
}
__device__ __forceinline__ void ldm_x4(uint32_t* r, uint32_t addr) {
    asm volatile("ldmatrix.sync.aligned.m8n8.x4.shared.b16 {%0,%1,%2,%3}, [%4];"
                 : "=r"(r[0]), "=r"(r[1]), "=r"(r[2]), "=r"(r[3]) : "r"(addr));
}
__device__ __forceinline__ void mma_f16(float* d, const uint32_t* a, uint32_t b0, uint32_t b1) {
    asm volatile(
        "mma.sync.aligned.m16n8k16.row.col.f32.f16.f16.f32 "
        "{%0,%1,%2,%3}, {%4,%5,%6,%7}, {%8,%9}, {%0,%1,%2,%3};"
        : "+f"(d[0]), "+f"(d[1]), "+f"(d[2]), "+f"(d[3])
        : "r"(a[0]), "r"(a[1]), "r"(a[2]), "r"(a[3]), "r"(b0), "r"(b1));
}

// ---------------------------------------------------------------------------
// Prep
// ---------------------------------------------------------------------------
__global__ void prep_a(const float* __restrict__ in) {
    int idx = blockIdx.x * blockDim.x + threadIdx.x;
    if (idx >= B_ * TP_ * C_) return;
    int c = idx & (C_ - 1);
    int r = idx >> 9;
    int b = r / TP_;
    int t = r - b * TP_;
    float v = (t < T_) ? in[((size_t)(b * T_ + t)) * C_ + c] : 0.0f;
    g_a16[idx] = __float2half_rn(v);
}

__global__ void prep_w(const float* __restrict__ W) {
    int idx = blockIdx.x * blockDim.x + threadIdx.x;   // over K_*NG
    if (idx >= K_ * NG) return;
    int k = idx / NG;
    int n = idx - k * NG;
    float v = W[idx];
    __half hi = __float2half_rn(v);
    __half lo = __float2half_rn(v - __half2float(hi));
    g_w_hi[(size_t)n * K_ + k] = hi;
    g_w_lo[(size_t)n * K_ + k] = lo;
}

// ---------------------------------------------------------------------------
// HMMA GEMM, fp16 2-product: gates = act(A16 @ (Wh + Wl) + bias)
// grid (NG/BN=12, (B_*T_)/BM=256), 256 threads (8 warps, 2(M) x 4(N))
// ---------------------------------------------------------------------------
__global__ void __launch_bounds__(256) gemm_mma(const float* __restrict__ bias) {
    extern __shared__ char smem[];
    const uint32_t sb = smem_u32(smem);
    const int tid  = threadIdx.x;
    const int wid  = tid >> 5;
    const int lane = tid & 31;

    const int bn  = blockIdx.x, bm = blockIdx.y;
    const int gm0 = bm * BM;
    const int b   = gm0 >> 12;
    const int t0  = gm0 & (T_ - 1);
    const int row0 = b * TP_ + t0;     // padded-row base; window overrun lands in pad row
    const int n0  = bn * BN;

    // per-thread static load coords (2 row/chunk pairs covering 128x32 tile)
    const int r0l = tid >> 2,         c0l = tid & 3;
    const int r1l = (tid + 256) >> 2, c1l = (tid + 256) & 3;
    const uint32_t so0 = r0l * 64 + ((c0l ^ (r0l & 3)) << 4);
    const uint32_t so1 = r1l * 64 + ((c1l ^ (r1l & 3)) << 4);

    auto issue = [&](int kk) {
        const uint32_t st = sb + (kk & (NSTAGE - 1)) * STAGE_BYTES;
        const int kb = kk * BK;
        const __half* a0 = g_a16 + (size_t)(row0 + r0l) * C_ + kb + c0l * 8;
        const __half* a1 = g_a16 + (size_t)(row0 + r1l) * C_ + kb + c1l * 8;
        const __half* w0 = g_w_hi + (size_t)(n0 + r0l) * K_ + kb + c0l * 8;
        const __half* w1 = g_w_hi + (size_t)(n0 + r1l) * K_ + kb + c1l * 8;
        const ptrdiff_t dW = g_w_lo - g_w_hi;
        cp16(st + so0,          a0);
        cp16(st + so1,          a1);
        cp16(st + 8192  + so0,  w0);
        cp16(st + 8192  + so1,  w1);
        cp16(st + 16384 + so0,  w0 + dW);
        cp16(st + 16384 + so1,  w1 + dW);
    };

    // Warp tile: 64(M) x 32(N)
    const int wm0 = (wid >> 2) * 64;
    const int wn0 = (wid & 3) * 32;

    float acc[4][4][4];
#pragma unroll
    for (int i = 0; i < 4; i++)
#pragma unroll
        for (int j = 0; j < 4; j++)
#pragma unroll
            for (int q = 0; q < 4; q++) acc[i][j][q] = 0.0f;

    issue(0); cp_commit();
    issue(1); cp_commit();
    issue(2); cp_commit();

    for (int kk = 0; kk < NKK; kk++) {
        cp_wait2();
        __syncthreads();
        if (kk + 3 < NKK) issue(kk + 3);
        cp_commit();                      // uniform group count

        const uint32_t st  = sb + (kk & (NSTAGE - 1)) * STAGE_BYTES;
        const uint32_t As = st, Whs = st + 8192, Wls = st + 16384;

#pragma unroll
        for (int ks = 0; ks < 2; ks++) {
            const int ch = ks * 2 + (lane >> 4);
            uint32_t a[4][4], wh[2][4], wl[2][4];
#pragma unroll
            for (int mt = 0; mt < 4; mt++) {
                int row = wm0 + mt * 16 + (lane & 15);
                uint32_t off = row * 64 + ((ch ^ (row & 3)) << 4);
                ldm_x4(a[mt], As + off);
            }
#pragma unroll
            for (int bt = 0; bt < 2; bt++) {
                int row = wn0 + bt * 16 + (lane & 15);
                uint32_t off = row * 64 + ((ch ^ (row & 3)) << 4);
                ldm_x4(wh[bt], Whs + off);
                ldm_x4(wl[bt], Wls + off);
            }
            // product 1: A * Whi
#pragma unroll
            for (int mt = 0; mt < 4; mt++)
#pragma unroll
                for (int nt = 0; nt < 4; nt++)
                    mma_f16(acc[mt][nt], a[mt], wh[nt >> 1][nt & 1], wh[nt >> 1][2 + (nt & 1)]);
            // product 2: A * Wlo
#pragma unroll
            for (int mt = 0; mt < 4; mt++)
#pragma unroll
                for (int nt = 0; nt < 4; nt++)
                    mma_f16(acc[mt][nt], a[mt], wl[nt >> 1][nt & 1], wl[nt >> 1][2 + (nt & 1)]);
        }
    }

    // Epilogue: bias + activation (uniform per CTA: n0 < U_ => tanh block)
    const bool is_tanh = (n0 < U_);
    const int grow = lane >> 2;
    const int gcol = (lane & 3) * 2;
#pragma unroll
    for (int mt = 0; mt < 4; mt++) {
#pragma unroll
        for (int nt = 0; nt < 4; nt++) {
            int n = n0 + wn0 + nt * 8 + gcol;
            float b0 = __ldg(bias + n);
            float b1 = __ldg(bias + n + 1);
#pragma unroll
            for (int h = 0; h < 2; h++) {
                int m = gm0 + wm0 + mt * 16 + grow + h * 8;
                float v0 = acc[mt][nt][2 * h]     + b0;
                float v1 = acc[mt][nt][2 * h + 1] + b1;
                if (is_tanh) {
                    float e0 = __expf(2.0f * v0), e1 = __expf(2.0f * v1);
                    v0 = 1.0f - 2.0f / (e0 + 1.0f);
                    v1 = 1.0f - 2.0f / (e1 + 1.0f);
                } else {
                    v0 = 1.0f / (1.0f + __expf(-v0));
                    v1 = 1.0f / (1.0f + __expf(-v1));
                }
                *(float2*)(g_gates + (size_t)m * NG + n) = make_float2(v0, v1);
            }
        }
    }
}

// ---------------------------------------------------------------------------
// Scan passes (float2, 128-thread blocks, grid (2, S_, B_) = 256 blocks)
// ---------------------------------------------------------------------------
__global__ void scan_partial() {
    int u = (blockIdx.x * blockDim.x + threadIdx.x) * 2;
    int s = blockIdx.y;
    int b = blockIdx.z;
    const float* gp = g_gates + ((size_t)(b * T_ + s * CH_)) * NG;
    float2 c = make_float2(0.f, 0.f), F = make_float2(1.f, 1.f);
    for (int t = 0; t < CH_; t++) {
        float2 x = *(const float2*)(gp + (size_t)t * NG + u);
        float2 f = *(const float2*)(gp + (size_t)t * NG + U_ + u);
        c.x = fmaf(f.x, c.x - x.x, x.x);
        c.y = fmaf(f.y, c.y - x.y, x.y);
        F.x *= f.x; F.y *= f.y;
    }
    int off = (b * S_ + s) * U_ + u;
    *(float2*)(g_cend  + off) = c;
    *(float2*)(g_fprod + off) = F;
}

__global__ void scan_carry() {
    int idx = blockIdx.x * blockDim.x + threadIdx.x;
    if (idx >= B_ * U_) return;
    int b = idx >> 9;
    int u = idx & (U_ - 1);
    float c = 0.0f;
    for (int s = 0; s < S_; s++) {
        int off = (b * S_ + s) * U_ + u;
        g_carry[off] = c;
        c = fmaf(g_fprod[off], c, g_cend[off]);
    }
}

__global__ void scan_final(float* __restrict__ out) {
    int u = (blockIdx.x * blockDim.x + threadIdx.x) * 2;
    int s = blockIdx.y;
    int b = blockIdx.z;
    const float* gp = g_gates + ((size_t)(b * T_ + s * CH_)) * NG;
    float* op = out + ((size_t)(b * T_ + s * CH_)) * U_;
    float2 c = *(const float2*)(g_carry + (b * S_ + s) * U_ + u);
    for (int t = 0; t < CH_; t++) {
        float2 x = *(const float2*)(gp + (size_t)t * NG + u);
        float2 f = *(const float2*)(gp + (size_t)t * NG + U_ + u);
        float2 o = *(const float2*)(gp + (size_t)t * NG + 2 * U_ + u);
        c.x = fmaf(f.x, c.x - x.x, x.x);
        c.y = fmaf(f.y, c.y - x.y, x.y);
        *(float2*)(op + (size_t)t * U_ + u) = make_float2(o.x * c.x, o.y * c.y);
    }
}

// ---------------------------------------------------------------------------
extern "C" void kernel_launch(void* const* d_in, const int* in_sizes, int n_in,
                              void* d_out, int out_size) {
    const float* in   = (const float*)d_in[0];
    const float* W    = (const float*)d_in[1];
    const float* bias = (const float*)d_in[2];
    float* out = (float*)d_out;

    int na = B_ * TP_ * C_;
    prep_a<<<(na + 255) / 256, 256>>>(in);
    prep_w<<<(K_ * NG + 255) / 256, 256>>>(W);

    cudaFuncSetAttribute(gemm_mma, cudaFuncAttributeMaxDynamicSharedMemorySize, SMEM_TOTAL);
    dim3 gGemm(NG / BN, (B_ * T_) / BM);   // (12, 256)
    gemm_mma<<<gGemm, 256, SMEM_TOTAL>>>(bias);

    dim3 gScan(U_ / 256, S_, B_);          // (2, 16, 8)
    scan_partial<<<gScan, 128>>>();
    scan_carry<<<(B_ * U_ + 255) / 256, 256>>>();
    scan_final<<<gScan, 128>>>(out);
}

// round 7
// speedup vs baseline: 3.0879x; 1.0861x over previous
#include <cuda_runtime.h>
#include <cuda_fp16.h>
#include <math.h>
#include <stdint.h>

#define B_  8
#define T_  4096
#define C_  512
#define U_  512
#define NG  1536            // 3*U
#define K_  1024            // 2*C
#define S_  32              // scan chunks
#define CH_ 128             // chunk length (S_*CH_ == T_)
#define TP_ 4097            // padded rows per batch (zero row at t=T)

#define BM  128
#define BN  128
#define BK  32
#define NKK (K_ / BK)       // 32 k-slices
#define NSTAGE 4
#define STAGE_BYTES 24576   // A 8K | Wh 8K | Wl 8K
#define SMEM_TOTAL (NSTAGE * STAGE_BYTES)

// ---- device scratch (allocation-free rule) --------------------------------
__device__ __align__(128) __half g_a16[B_ * TP_ * C_];
__device__ __align__(128) __half g_w_hi[NG * K_];   // [n][k]
__device__ __align__(128) __half g_w_lo[NG * K_];
__device__ __align__(128) __half g_gates16[(size_t)B_ * T_ * NG]; // fp16 gates
__device__ float g_cend[B_ * S_ * U_];
__device__ float g_fprod[B_ * S_ * U_];
__device__ float g_carry[B_ * S_ * U_];

// ---------------------------------------------------------------------------
__device__ __forceinline__ uint32_t smem_u32(const void* p) {
    uint32_t a;
    asm("{ .reg .u64 t; cvta.to.shared.u64 t, %1; cvt.u32.u64 %0, t; }" : "=r"(a) : "l"(p));
    return a;
}
__device__ __forceinline__ void cp16(uint32_t saddr, const void* gaddr) {
    asm volatile("cp.async.cg.shared.global [%0], [%1], 16;" :: "r"(saddr), "l"(gaddr));
}
__device__ __forceinline__ void cp_commit() {
    asm volatile("cp.async.commit_group;" ::: "memory");
}
__device__ __forceinline__ void cp_wait2() {
    asm volatile("cp.async.wait_group 2;" ::: "memory");
}
__device__ __forceinline__ void ldm_x4(uint32_t* r, uint32_t addr) {
    asm volatile("ldmatrix.sync.aligned.m8n8.x4.shared.b16 {%0,%1,%2,%3}, [%4];"
                 : "=r"(r[0]), "=r"(r[1]), "=r"(r[2]), "=r"(r[3]) : "r"(addr));
}
__device__ __forceinline__ void mma_f16(float* d, const uint32_t* a, uint32_t b0, uint32_t b1) {
    asm volatile(
        "mma.sync.aligned.m16n8k16.row.col.f32.f16.f16.f32 "
        "{%0,%1,%2,%3}, {%4,%5,%6,%7}, {%8,%9}, {%0,%1,%2,%3};"
        : "+f"(d[0]), "+f"(d[1]), "+f"(d[2]), "+f"(d[3])
        : "r"(a[0]), "r"(a[1]), "r"(a[2]), "r"(a[3]), "r"(b0), "r"(b1));
}

// ---------------------------------------------------------------------------
// Prep
// ---------------------------------------------------------------------------
__global__ void prep_a(const float* __restrict__ in) {
    int idx = blockIdx.x * blockDim.x + threadIdx.x;
    if (idx >= B_ * TP_ * C_) return;
    int c = idx & (C_ - 1);
    int r = idx >> 9;
    int b = r / TP_;
    int t = r - b * TP_;
    float v = (t < T_) ? in[((size_t)(b * T_ + t)) * C_ + c] : 0.0f;
    g_a16[idx] = __float2half_rn(v);
}

__global__ void prep_w(const float* __restrict__ W) {
    int idx = blockIdx.x * blockDim.x + threadIdx.x;   // over K_*NG
    if (idx >= K_ * NG) return;
    int k = idx / NG;
    int n = idx - k * NG;
    float v = W[idx];
    __half hi = __float2half_rn(v);
    __half lo = __float2half_rn(v - __half2float(hi));
    g_w_hi[(size_t)n * K_ + k] = hi;
    g_w_lo[(size_t)n * K_ + k] = lo;
}

// ---------------------------------------------------------------------------
// HMMA GEMM, fp16 2-product: gates = act(A16 @ (Wh + Wl) + bias)
// grid (NG/BN=12, (B_*T_)/BM=256), 256 threads (8 warps, 2(M) x 4(N))
// ---------------------------------------------------------------------------
__global__ void __launch_bounds__(256) gemm_mma(const float* __restrict__ bias) {
    extern __shared__ char smem[];
    const uint32_t sb = smem_u32(smem);
    const int tid  = threadIdx.x;
    const int wid  = tid >> 5;
    const int lane = tid & 31;

    const int bn  = blockIdx.x, bm = blockIdx.y;
    const int gm0 = bm * BM;
    const int b   = gm0 >> 12;
    const int t0  = gm0 & (T_ - 1);
    const int row0 = b * TP_ + t0;     // padded-row base; window overrun lands in pad row
    const int n0  = bn * BN;

    // per-thread static load coords (2 row/chunk pairs covering 128x32 tile)
    const int r0l = tid >> 2,         c0l = tid & 3;
    const int r1l = (tid + 256) >> 2, c1l = (tid + 256) & 3;
    const uint32_t so0 = r0l * 64 + ((c0l ^ (r0l & 3)) << 4);
    const uint32_t so1 = r1l * 64 + ((c1l ^ (r1l & 3)) << 4);

    auto issue = [&](int kk) {
        const uint32_t st = sb + (kk & (NSTAGE - 1)) * STAGE_BYTES;
        const int kb = kk * BK;
        const __half* a0 = g_a16 + (size_t)(row0 + r0l) * C_ + kb + c0l * 8;
        const __half* a1 = g_a16 + (size_t)(row0 + r1l) * C_ + kb + c1l * 8;
        const __half* w0 = g_w_hi + (size_t)(n0 + r0l) * K_ + kb + c0l * 8;
        const __half* w1 = g_w_hi + (size_t)(n0 + r1l) * K_ + kb + c1l * 8;
        const ptrdiff_t dW = g_w_lo - g_w_hi;
        cp16(st + so0,          a0);
        cp16(st + so1,          a1);
        cp16(st + 8192  + so0,  w0);
        cp16(st + 8192  + so1,  w1);
        cp16(st + 16384 + so0,  w0 + dW);
        cp16(st + 16384 + so1,  w1 + dW);
    };

    // Warp tile: 64(M) x 32(N)
    const int wm0 = (wid >> 2) * 64;
    const int wn0 = (wid & 3) * 32;

    float acc[4][4][4];
#pragma unroll
    for (int i = 0; i < 4; i++)
#pragma unroll
        for (int j = 0; j < 4; j++)
#pragma unroll
            for (int q = 0; q < 4; q++) acc[i][j][q] = 0.0f;

    issue(0); cp_commit();
    issue(1); cp_commit();
    issue(2); cp_commit();

    for (int kk = 0; kk < NKK; kk++) {
        cp_wait2();
        __syncthreads();
        if (kk + 3 < NKK) issue(kk + 3);
        cp_commit();                      // uniform group count

        const uint32_t st  = sb + (kk & (NSTAGE - 1)) * STAGE_BYTES;
        const uint32_t As = st, Whs = st + 8192, Wls = st + 16384;

#pragma unroll
        for (int ks = 0; ks < 2; ks++) {
            const int ch = ks * 2 + (lane >> 4);
            uint32_t a[4][4], wh[2][4], wl[2][4];
#pragma unroll
            for (int mt = 0; mt < 4; mt++) {
                int row = wm0 + mt * 16 + (lane & 15);
                uint32_t off = row * 64 + ((ch ^ (row & 3)) << 4);
                ldm_x4(a[mt], As + off);
            }
#pragma unroll
            for (int bt = 0; bt < 2; bt++) {
                int row = wn0 + bt * 16 + (lane & 15);
                uint32_t off = row * 64 + ((ch ^ (row & 3)) << 4);
                ldm_x4(wh[bt], Whs + off);
                ldm_x4(wl[bt], Wls + off);
            }
            // product 1: A * Whi
#pragma unroll
            for (int mt = 0; mt < 4; mt++)
#pragma unroll
                for (int nt = 0; nt < 4; nt++)
                    mma_f16(acc[mt][nt], a[mt], wh[nt >> 1][nt & 1], wh[nt >> 1][2 + (nt & 1)]);
            // product 2: A * Wlo
#pragma unroll
            for (int mt = 0; mt < 4; mt++)
#pragma unroll
                for (int nt = 0; nt < 4; nt++)
                    mma_f16(acc[mt][nt], a[mt], wl[nt >> 1][nt & 1], wl[nt >> 1][2 + (nt & 1)]);
        }
    }

    // Epilogue: bias + activation + fp16 pack (uniform per CTA: n0 < U_ => tanh)
    const bool is_tanh = (n0 < U_);
    const int grow = lane >> 2;
    const int gcol = (lane & 3) * 2;
#pragma unroll
    for (int mt = 0; mt < 4; mt++) {
#pragma unroll
        for (int nt = 0; nt < 4; nt++) {
            int n = n0 + wn0 + nt * 8 + gcol;
            float b0 = __ldg(bias + n);
            float b1 = __ldg(bias + n + 1);
#pragma unroll
            for (int h = 0; h < 2; h++) {
                int m = gm0 + wm0 + mt * 16 + grow + h * 8;
                float v0 = acc[mt][nt][2 * h]     + b0;
                float v1 = acc[mt][nt][2 * h + 1] + b1;
                if (is_tanh) {
                    float e0 = __expf(2.0f * v0), e1 = __expf(2.0f * v1);
                    v0 = 1.0f - 2.0f / (e0 + 1.0f);
                    v1 = 1.0f - 2.0f / (e1 + 1.0f);
                } else {
                    v0 = 1.0f / (1.0f + __expf(-v0));
                    v1 = 1.0f / (1.0f + __expf(-v1));
                }
                *(__half2*)(g_gates16 + (size_t)m * NG + n) = __floats2half2_rn(v0, v1);
            }
        }
    }
}

// ---------------------------------------------------------------------------
// Scan passes: fp16 gates, fp32 math. 256 threads/block = 2 channels each.
// grid (1, S_, B_) = 256 blocks
// ---------------------------------------------------------------------------
__global__ void __launch_bounds__(256) scan_partial() {
    int u = threadIdx.x * 2;
    int s = blockIdx.y;
    int b = blockIdx.z;
    const __half* gp = g_gates16 + ((size_t)(b * T_ + s * CH_)) * NG;
    float2 c = make_float2(0.f, 0.f), F = make_float2(1.f, 1.f);
    for (int t = 0; t < CH_; t++) {
        float2 x = __half22float2(*(const __half2*)(gp + (size_t)t * NG + u));
        float2 f = __half22float2(*(const __half2*)(gp + (size_t)t * NG + U_ + u));
        c.x = fmaf(f.x, c.x - x.x, x.x);
        c.y = fmaf(f.y, c.y - x.y, x.y);
        F.x *= f.x; F.y *= f.y;
    }
    int off = (b * S_ + s) * U_ + u;
    *(float2*)(g_cend  + off) = c;
    *(float2*)(g_fprod + off) = F;
}

__global__ void scan_carry() {
    int idx = blockIdx.x * blockDim.x + threadIdx.x;
    if (idx >= B_ * U_) return;
    int b = idx >> 9;
    int u = idx & (U_ - 1);
    float c = 0.0f;
    for (int s = 0; s < S_; s++) {
        int off = (b * S_ + s) * U_ + u;
        g_carry[off] = c;
        c = fmaf(g_fprod[off], c, g_cend[off]);
    }
}

__global__ void __launch_bounds__(256) scan_final(float* __restrict__ out) {
    int u = threadIdx.x * 2;
    int s = blockIdx.y;
    int b = blockIdx.z;
    const __half* gp = g_gates16 + ((size_t)(b * T_ + s * CH_)) * NG;
    float* op = out + ((size_t)(b * T_ + s * CH_)) * U_;
    float2 c = *(const float2*)(g_carry + (b * S_ + s) * U_ + u);
    for (int t = 0; t < CH_; t++) {
        float2 x = __half22float2(*(const __half2*)(gp + (size_t)t * NG + u));
        float2 f = __half22float2(*(const __half2*)(gp + (size_t)t * NG + U_ + u));
        float2 o = __half22float2(*(const __half2*)(gp + (size_t)t * NG + 2 * U_ + u));
        c.x = fmaf(f.x, c.x - x.x, x.x);
        c.y = fmaf(f.y, c.y - x.y, x.y);
        *(float2*)(op + (size_t)t * U_ + u) = make_float2(o.x * c.x, o.y * c.y);
    }
}

// ---------------------------------------------------------------------------
extern "C" void kernel_launch(void* const* d_in, const int* in_sizes, int n_in,
                              void* d_out, int out_size) {
    const float* in   = (const float*)d_in[0];
    const float* W    = (const float*)d_in[1];
    const float* bias = (const float*)d_in[2];
    float* out = (float*)d_out;

    int na = B_ * TP_ * C_;
    prep_a<<<(na + 255) / 256, 256>>>(in);
    prep_w<<<(K_ * NG + 255) / 256, 256>>>(W);

    cudaFuncSetAttribute(gemm_mma, cudaFuncAttributeMaxDynamicSharedMemorySize, SMEM_TOTAL);
    dim3 gGemm(NG / BN, (B_ * T_) / BM);   // (12, 256)
    gemm_mma<<<gGemm, 256, SMEM_TOTAL>>>(bias);

    dim3 gScan(1, S_, B_);                 // 256 blocks
    scan_partial<<<gScan, 256>>>();
    scan_carry<<<(B_ * U_ + 255) / 256, 256>>>();
    scan_final<<<gScan, 256>>>(out);
}

// round 8
// speedup vs baseline: 4.3653x; 1.4137x over previous
#include <cuda_runtime.h>
#include <cuda_fp16.h>
#include <math.h>
#include <stdint.h>

#define B_  8
#define T_  4096
#define C_  512
#define U_  512
#define NG  1536            // 3*U
#define K_  1024            // 2*C
#define S_  32              // scan chunks
#define CH_ 128             // chunk length (S_*CH_ == T_)
#define TP_ 4097            // padded rows per batch (zero row at t=T)

#define BM  128
#define BN  128
#define BK  32
#define NKK (K_ / BK)       // 32 k-slices
#define NSTAGE 4
#define STAGE_BYTES 16384   // A 8K | W 8K
#define SMEM_TOTAL (NSTAGE * STAGE_BYTES)

// ---- device scratch (allocation-free rule) --------------------------------
__device__ __align__(128) __half g_a16[B_ * TP_ * C_];
__device__ __align__(128) __half g_w16[NG * K_];    // [n][k]
__device__ __align__(128) __half g_gates16[(size_t)B_ * T_ * NG]; // fp16 gates
__device__ float g_cend[B_ * S_ * U_];
__device__ float g_fprod[B_ * S_ * U_];
__device__ float g_carry[B_ * S_ * U_];

// ---------------------------------------------------------------------------
__device__ __forceinline__ uint32_t smem_u32(const void* p) {
    uint32_t a;
    asm("{ .reg .u64 t; cvta.to.shared.u64 t, %1; cvt.u32.u64 %0, t; }" : "=r"(a) : "l"(p));
    return a;
}
__device__ __forceinline__ void cp16(uint32_t saddr, const void* gaddr) {
    asm volatile("cp.async.cg.shared.global [%0], [%1], 16;" :: "r"(saddr), "l"(gaddr));
}
__device__ __forceinline__ void cp_commit() {
    asm volatile("cp.async.commit_group;" ::: "memory");
}
__device__ __forceinline__ void cp_wait2() {
    asm volatile("cp.async.wait_group 2;" ::: "memory");
}
__device__ __forceinline__ void ldm_x4(uint32_t* r, uint32_t addr) {
    asm volatile("ldmatrix.sync.aligned.m8n8.x4.shared.b16 {%0,%1,%2,%3}, [%4];"
                 : "=r"(r[0]), "=r"(r[1]), "=r"(r[2]), "=r"(r[3]) : "r"(addr));
}
__device__ __forceinline__ void mma_f16(float* d, const uint32_t* a, uint32_t b0, uint32_t b1) {
    asm volatile(
        "mma.sync.aligned.m16n8k16.row.col.f32.f16.f16.f32 "
        "{%0,%1,%2,%3}, {%4,%5,%6,%7}, {%8,%9}, {%0,%1,%2,%3};"
        : "+f"(d[0]), "+f"(d[1]), "+f"(d[2]), "+f"(d[3])
        : "r"(a[0]), "r"(a[1]), "r"(a[2]), "r"(a[3]), "r"(b0), "r"(b1));
}

// ---------------------------------------------------------------------------
// Prep
// ---------------------------------------------------------------------------
__global__ void prep_a(const float* __restrict__ in) {
    int idx = blockIdx.x * blockDim.x + threadIdx.x;
    if (idx >= B_ * TP_ * C_) return;
    int c = idx & (C_ - 1);
    int r = idx >> 9;
    int b = r / TP_;
    int t = r - b * TP_;
    float v = (t < T_) ? in[((size_t)(b * T_ + t)) * C_ + c] : 0.0f;
    g_a16[idx] = __float2half_rn(v);
}

__global__ void prep_w(const float* __restrict__ W) {
    int idx = blockIdx.x * blockDim.x + threadIdx.x;   // over K_*NG
    if (idx >= K_ * NG) return;
    int k = idx / NG;
    int n = idx - k * NG;
    g_w16[(size_t)n * K_ + k] = __float2half_rn(W[idx]);
}

// ---------------------------------------------------------------------------
// HMMA GEMM, single-product fp16: gates = act(A16 @ W16 + bias)
// grid (NG/BN=12, (B_*T_)/BM=256), 256 threads (8 warps, 2(M) x 4(N))
// ---------------------------------------------------------------------------
__global__ void __launch_bounds__(256) gemm_mma(const float* __restrict__ bias) {
    extern __shared__ char smem[];
    const uint32_t sb = smem_u32(smem);
    const int tid  = threadIdx.x;
    const int wid  = tid >> 5;
    const int lane = tid & 31;

    const int bn  = blockIdx.x, bm = blockIdx.y;
    const int gm0 = bm * BM;
    const int b   = gm0 >> 12;
    const int t0  = gm0 & (T_ - 1);
    const int row0 = b * TP_ + t0;     // padded-row base; window overrun lands in pad row
    const int n0  = bn * BN;

    // per-thread static load coords (2 row/chunk pairs covering 128x32 tile)
    const int r0l = tid >> 2,         c0l = tid & 3;
    const int r1l = (tid + 256) >> 2, c1l = (tid + 256) & 3;
    const uint32_t so0 = r0l * 64 + ((c0l ^ (r0l & 3)) << 4);
    const uint32_t so1 = r1l * 64 + ((c1l ^ (r1l & 3)) << 4);

    auto issue = [&](int kk) {
        const uint32_t st = sb + (kk & (NSTAGE - 1)) * STAGE_BYTES;
        const int kb = kk * BK;
        const __half* a0 = g_a16 + (size_t)(row0 + r0l) * C_ + kb + c0l * 8;
        const __half* a1 = g_a16 + (size_t)(row0 + r1l) * C_ + kb + c1l * 8;
        const __half* w0 = g_w16 + (size_t)(n0 + r0l) * K_ + kb + c0l * 8;
        const __half* w1 = g_w16 + (size_t)(n0 + r1l) * K_ + kb + c1l * 8;
        cp16(st + so0,         a0);
        cp16(st + so1,         a1);
        cp16(st + 8192 + so0,  w0);
        cp16(st + 8192 + so1,  w1);
    };

    // Warp tile: 64(M) x 32(N)
    const int wm0 = (wid >> 2) * 64;
    const int wn0 = (wid & 3) * 32;

    float acc[4][4][4];
#pragma unroll
    for (int i = 0; i < 4; i++)
#pragma unroll
        for (int j = 0; j < 4; j++)
#pragma unroll
            for (int q = 0; q < 4; q++) acc[i][j][q] = 0.0f;

    issue(0); cp_commit();
    issue(1); cp_commit();
    issue(2); cp_commit();

    for (int kk = 0; kk < NKK; kk++) {
        cp_wait2();
        __syncthreads();
        if (kk + 3 < NKK) issue(kk + 3);
        cp_commit();                      // uniform group count

        const uint32_t st = sb + (kk & (NSTAGE - 1)) * STAGE_BYTES;
        const uint32_t As = st, Ws = st + 8192;

#pragma unroll
        for (int ks = 0; ks < 2; ks++) {
            const int ch = ks * 2 + (lane >> 4);
            uint32_t a[4][4], w[2][4];
#pragma unroll
            for (int mt = 0; mt < 4; mt++) {
                int row = wm0 + mt * 16 + (lane & 15);
                uint32_t off = row * 64 + ((ch ^ (row & 3)) << 4);
                ldm_x4(a[mt], As + off);
            }
#pragma unroll
            for (int bt = 0; bt < 2; bt++) {
                int row = wn0 + bt * 16 + (lane & 15);
                uint32_t off = row * 64 + ((ch ^ (row & 3)) << 4);
                ldm_x4(w[bt], Ws + off);
            }
#pragma unroll
            for (int mt = 0; mt < 4; mt++)
#pragma unroll
                for (int nt = 0; nt < 4; nt++)
                    mma_f16(acc[mt][nt], a[mt], w[nt >> 1][nt & 1], w[nt >> 1][2 + (nt & 1)]);
        }
    }

    // Epilogue: bias + activation + fp16 pack (uniform per CTA: n0 < U_ => tanh)
    const bool is_tanh = (n0 < U_);
    const int grow = lane >> 2;
    const int gcol = (lane & 3) * 2;
#pragma unroll
    for (int mt = 0; mt < 4; mt++) {
#pragma unroll
        for (int nt = 0; nt < 4; nt++) {
            int n = n0 + wn0 + nt * 8 + gcol;
            float b0 = __ldg(bias + n);
            float b1 = __ldg(bias + n + 1);
#pragma unroll
            for (int h = 0; h < 2; h++) {
                int m = gm0 + wm0 + mt * 16 + grow + h * 8;
                float v0 = acc[mt][nt][2 * h]     + b0;
                float v1 = acc[mt][nt][2 * h + 1] + b1;
                if (is_tanh) {
                    float e0 = __expf(2.0f * v0), e1 = __expf(2.0f * v1);
                    v0 = 1.0f - 2.0f / (e0 + 1.0f);
                    v1 = 1.0f - 2.0f / (e1 + 1.0f);
                } else {
                    v0 = 1.0f / (1.0f + __expf(-v0));
                    v1 = 1.0f / (1.0f + __expf(-v1));
                }
                *(__half2*)(g_gates16 + (size_t)m * NG + n) = __floats2half2_rn(v0, v1);
            }
        }
    }
}

// ---------------------------------------------------------------------------
// Scan passes: fp16 gates, fp32 math. 256 threads/block = 2 channels each.
// grid (1, S_, B_) = 256 blocks
// ---------------------------------------------------------------------------
__global__ void __launch_bounds__(256) scan_partial() {
    int u = threadIdx.x * 2;
    int s = blockIdx.y;
    int b = blockIdx.z;
    const __half* gp = g_gates16 + ((size_t)(b * T_ + s * CH_)) * NG;
    float2 c = make_float2(0.f, 0.f), F = make_float2(1.f, 1.f);
    for (int t = 0; t < CH_; t++) {
        float2 x = __half22float2(*(const __half2*)(gp + (size_t)t * NG + u));
        float2 f = __half22float2(*(const __half2*)(gp + (size_t)t * NG + U_ + u));
        c.x = fmaf(f.x, c.x - x.x, x.x);
        c.y = fmaf(f.y, c.y - x.y, x.y);
        F.x *= f.x; F.y *= f.y;
    }
    int off = (b * S_ + s) * U_ + u;
    *(float2*)(g_cend  + off) = c;
    *(float2*)(g_fprod + off) = F;
}

__global__ void scan_carry() {
    int idx = blockIdx.x * blockDim.x + threadIdx.x;
    if (idx >= B_ * U_) return;
    int b = idx >> 9;
    int u = idx & (U_ - 1);
    float c = 0.0f;
    for (int s = 0; s < S_; s++) {
        int off = (b * S_ + s) * U_ + u;
        g_carry[off] = c;
        c = fmaf(g_fprod[off], c, g_cend[off]);
    }
}

__global__ void __launch_bounds__(256) scan_final(float* __restrict__ out) {
    int u = threadIdx.x * 2;
    int s = blockIdx.y;
    int b = blockIdx.z;
    const __half* gp = g_gates16 + ((size_t)(b * T_ + s * CH_)) * NG;
    float* op = out + ((size_t)(b * T_ + s * CH_)) * U_;
    float2 c = *(const float2*)(g_carry + (b * S_ + s) * U_ + u);
    for (int t = 0; t < CH_; t++) {
        float2 x = __half22float2(*(const __half2*)(gp + (size_t)t * NG + u));
        float2 f = __half22float2(*(const __half2*)(gp + (size_t)t * NG + U_ + u));
        float2 o = __half22float2(*(const __half2*)(gp + (size_t)t * NG + 2 * U_ + u));
        c.x = fmaf(f.x, c.x - x.x, x.x);
        c.y = fmaf(f.y, c.y - x.y, x.y);
        *(float2*)(op + (size_t)t * U_ + u) = make_float2(o.x * c.x, o.y * c.y);
    }
}

// ---------------------------------------------------------------------------
extern "C" void kernel_launch(void* const* d_in, const int* in_sizes, int n_in,
                              void* d_out, int out_size) {
    const float* in   = (const float*)d_in[0];
    const float* W    = (const float*)d_in[1];
    const float* bias = (const float*)d_in[2];
    float* out = (float*)d_out;

    int na = B_ * TP_ * C_;
    prep_a<<<(na + 255) / 256, 256>>>(in);
    prep_w<<<(K_ * NG + 255) / 256, 256>>>(W);

    cudaFuncSetAttribute(gemm_mma, cudaFuncAttributeMaxDynamicSharedMemorySize, SMEM_TOTAL);
    dim3 gGemm(NG / BN, (B_ * T_) / BM);   // (12, 256)
    gemm_mma<<<gGemm, 256, SMEM_TOTAL>>>(bias);

    dim3 gScan(1, S_, B_);                 // 256 blocks
    scan_partial<<<gScan, 256>>>();
    scan_carry<<<(B_ * U_ + 255) / 256, 256>>>();
    scan_final<<<gScan, 256>>>(out);
}

// round 9
// speedup vs baseline: 4.6701x; 1.0698x over previous
#include <cuda_runtime.h>
#include <cuda_fp16.h>
#include <math.h>
#include <stdint.h>

#define B_  8
#define T_  4096
#define C_  512
#define U_  512
#define NG  1536            // 3*U
#define K_  1024            // 2*C
#define S_  32              // scan chunks
#define CH_ 128             // chunk length (S_*CH_ == T_)
#define TP_ 4097            // padded rows per batch (zero row at t=T)

#define BM  128
#define BN  128
#define BK  32
#define NKK (K_ / BK)       // 32 k-slices
#define NSTAGE 4
#define STAGE_BYTES 16384   // A 8K | W 8K
#define SMEM_TOTAL (NSTAGE * STAGE_BYTES)

// ---- device scratch (allocation-free rule) --------------------------------
__device__ __align__(128) __half g_a16[B_ * TP_ * C_];
__device__ __align__(128) __half g_w16[NG * K_];    // [n][k]
__device__ __align__(128) __half g_gates16[(size_t)B_ * T_ * NG]; // fp16 gates
__device__ float g_cend[B_ * S_ * U_];
__device__ float g_fprod[B_ * S_ * U_];
__device__ float g_carry[B_ * S_ * U_];

// ---------------------------------------------------------------------------
__device__ __forceinline__ uint32_t smem_u32(const void* p) {
    uint32_t a;
    asm("{ .reg .u64 t; cvta.to.shared.u64 t, %1; cvt.u32.u64 %0, t; }" : "=r"(a) : "l"(p));
    return a;
}
__device__ __forceinline__ void cp16(uint32_t saddr, const void* gaddr) {
    asm volatile("cp.async.cg.shared.global [%0], [%1], 16;" :: "r"(saddr), "l"(gaddr));
}
__device__ __forceinline__ void cp_commit() {
    asm volatile("cp.async.commit_group;" ::: "memory");
}
__device__ __forceinline__ void cp_wait2() {
    asm volatile("cp.async.wait_group 2;" ::: "memory");
}
__device__ __forceinline__ void ldm_x4(uint32_t* r, uint32_t addr) {
    asm volatile("ldmatrix.sync.aligned.m8n8.x4.shared.b16 {%0,%1,%2,%3}, [%4];"
                 : "=r"(r[0]), "=r"(r[1]), "=r"(r[2]), "=r"(r[3]) : "r"(addr));
}
__device__ __forceinline__ void mma_f16(float* d, const uint32_t* a, uint32_t b0, uint32_t b1) {
    asm volatile(
        "mma.sync.aligned.m16n8k16.row.col.f32.f16.f16.f32 "
        "{%0,%1,%2,%3}, {%4,%5,%6,%7}, {%8,%9}, {%0,%1,%2,%3};"
        : "+f"(d[0]), "+f"(d[1]), "+f"(d[2]), "+f"(d[3])
        : "r"(a[0]), "r"(a[1]), "r"(a[2]), "r"(a[3]), "r"(b0), "r"(b1));
}

// ---------------------------------------------------------------------------
// Prep
// ---------------------------------------------------------------------------
__global__ void prep_a(const float* __restrict__ in) {
    int idx = blockIdx.x * blockDim.x + threadIdx.x;
    if (idx >= B_ * TP_ * C_) return;
    int c = idx & (C_ - 1);
    int r = idx >> 9;
    int b = r / TP_;
    int t = r - b * TP_;
    float v = (t < T_) ? in[((size_t)(b * T_ + t)) * C_ + c] : 0.0f;
    g_a16[idx] = __float2half_rn(v);
}

__global__ void prep_w(const float* __restrict__ W) {
    int idx = blockIdx.x * blockDim.x + threadIdx.x;   // over K_*NG
    if (idx >= K_ * NG) return;
    int k = idx / NG;
    int n = idx - k * NG;
    g_w16[(size_t)n * K_ + k] = __float2half_rn(W[idx]);
}

// ---------------------------------------------------------------------------
// HMMA GEMM, single-product fp16, 2 CTAs/SM: gates = act(A16 @ W16 + bias)
// grid (NG/BN=12, (B_*T_)/BM=256), 256 threads (8 warps, 2(M) x 4(N))
// ---------------------------------------------------------------------------
__global__ void __launch_bounds__(256, 2) gemm_mma(const float* __restrict__ bias) {
    extern __shared__ char smem[];
    const uint32_t sb = smem_u32(smem);
    const int tid  = threadIdx.x;
    const int wid  = tid >> 5;
    const int lane = tid & 31;

    const int bn  = blockIdx.x, bm = blockIdx.y;
    const int gm0 = bm * BM;
    const int b   = gm0 >> 12;
    const int t0  = gm0 & (T_ - 1);
    const int row0 = b * TP_ + t0;     // padded-row base; window overrun lands in pad row
    const int n0  = bn * BN;

    // per-thread static load coords (2 row/chunk pairs covering 128x32 tile)
    const int r0l = tid >> 2,         c0l = tid & 3;
    const int r1l = (tid + 256) >> 2, c1l = (tid + 256) & 3;
    const uint32_t so0 = r0l * 64 + ((c0l ^ (r0l & 3)) << 4);
    const uint32_t so1 = r1l * 64 + ((c1l ^ (r1l & 3)) << 4);

    // strength-reduced global pointers, advanced by BK per slice
    const __half* pa0 = g_a16 + (size_t)(row0 + r0l) * C_ + c0l * 8;
    const __half* pa1 = g_a16 + (size_t)(row0 + r1l) * C_ + c1l * 8;
    const __half* pw0 = g_w16 + (size_t)(n0 + r0l) * K_ + c0l * 8;
    const __half* pw1 = g_w16 + (size_t)(n0 + r1l) * K_ + c1l * 8;

    auto issue = [&](int kk) {
        const uint32_t st = sb + (kk & (NSTAGE - 1)) * STAGE_BYTES;
        const int kb = kk * BK;
        cp16(st + so0,         pa0 + kb);
        cp16(st + so1,         pa1 + kb);
        cp16(st + 8192 + so0,  pw0 + kb);
        cp16(st + 8192 + so1,  pw1 + kb);
    };

    // Warp tile: 64(M) x 32(N)
    const int wm0 = (wid >> 2) * 64;
    const int wn0 = (wid & 3) * 32;

    float acc[4][4][4];
#pragma unroll
    for (int i = 0; i < 4; i++)
#pragma unroll
        for (int j = 0; j < 4; j++)
#pragma unroll
            for (int q = 0; q < 4; q++) acc[i][j][q] = 0.0f;

    issue(0); cp_commit();
    issue(1); cp_commit();
    issue(2); cp_commit();

    for (int kk = 0; kk < NKK; kk++) {
        cp_wait2();
        __syncthreads();
        if (kk + 3 < NKK) issue(kk + 3);
        cp_commit();                      // uniform group count

        const uint32_t st = sb + (kk & (NSTAGE - 1)) * STAGE_BYTES;
        const uint32_t As = st, Ws = st + 8192;

#pragma unroll
        for (int ks = 0; ks < 2; ks++) {
            const int ch = ks * 2 + (lane >> 4);
            uint32_t a[4][4], w[2][4];
#pragma unroll
            for (int mt = 0; mt < 4; mt++) {
                int row = wm0 + mt * 16 + (lane & 15);
                uint32_t off = row * 64 + ((ch ^ (row & 3)) << 4);
                ldm_x4(a[mt], As + off);
            }
#pragma unroll
            for (int bt = 0; bt < 2; bt++) {
                int row = wn0 + bt * 16 + (lane & 15);
                uint32_t off = row * 64 + ((ch ^ (row & 3)) << 4);
                ldm_x4(w[bt], Ws + off);
            }
#pragma unroll
            for (int mt = 0; mt < 4; mt++)
#pragma unroll
                for (int nt = 0; nt < 4; nt++)
                    mma_f16(acc[mt][nt], a[mt], w[nt >> 1][nt & 1], w[nt >> 1][2 + (nt & 1)]);
        }
    }

    // Epilogue: bias + activation + fp16 pack (uniform per CTA: n0 < U_ => tanh)
    const bool is_tanh = (n0 < U_);
    const int grow = lane >> 2;
    const int gcol = (lane & 3) * 2;
#pragma unroll
    for (int mt = 0; mt < 4; mt++) {
#pragma unroll
        for (int nt = 0; nt < 4; nt++) {
            int n = n0 + wn0 + nt * 8 + gcol;
            float b0 = __ldg(bias + n);
            float b1 = __ldg(bias + n + 1);
#pragma unroll
            for (int h = 0; h < 2; h++) {
                int m = gm0 + wm0 + mt * 16 + grow + h * 8;
                float v0 = acc[mt][nt][2 * h]     + b0;
                float v1 = acc[mt][nt][2 * h + 1] + b1;
                if (is_tanh) {
                    float e0 = __expf(2.0f * v0), e1 = __expf(2.0f * v1);
                    v0 = 1.0f - 2.0f / (e0 + 1.0f);
                    v1 = 1.0f - 2.0f / (e1 + 1.0f);
                } else {
                    v0 = 1.0f / (1.0f + __expf(-v0));
                    v1 = 1.0f / (1.0f + __expf(-v1));
                }
                *(__half2*)(g_gates16 + (size_t)m * NG + n) = __floats2half2_rn(v0, v1);
            }
        }
    }
}

// ---------------------------------------------------------------------------
// Scan passes: fp16 gates, fp32 math. 256 threads/block = 2 channels each.
// grid (1, S_, B_) = 256 blocks
// ---------------------------------------------------------------------------
__global__ void __launch_bounds__(256) scan_partial() {
    int u = threadIdx.x * 2;
    int s = blockIdx.y;
    int b = blockIdx.z;
    const __half* gp = g_gates16 + ((size_t)(b * T_ + s * CH_)) * NG;
    float2 c = make_float2(0.f, 0.f), F = make_float2(1.f, 1.f);
    for (int t = 0; t < CH_; t++) {
        float2 x = __half22float2(*(const __half2*)(gp + (size_t)t * NG + u));
        float2 f = __half22float2(*(const __half2*)(gp + (size_t)t * NG + U_ + u));
        c.x = fmaf(f.x, c.x - x.x, x.x);
        c.y = fmaf(f.y, c.y - x.y, x.y);
        F.x *= f.x; F.y *= f.y;
    }
    int off = (b * S_ + s) * U_ + u;
    *(float2*)(g_cend  + off) = c;
    *(float2*)(g_fprod + off) = F;
}

__global__ void scan_carry() {
    int idx = blockIdx.x * blockDim.x + threadIdx.x;
    if (idx >= B_ * U_) return;
    int b = idx >> 9;
    int u = idx & (U_ - 1);
    float c = 0.0f;
    for (int s = 0; s < S_; s++) {
        int off = (b * S_ + s) * U_ + u;
        g_carry[off] = c;
        c = fmaf(g_fprod[off], c, g_cend[off]);
    }
}

__global__ void __launch_bounds__(256) scan_final(float* __restrict__ out) {
    int u = threadIdx.x * 2;
    int s = blockIdx.y;
    int b = blockIdx.z;
    const __half* gp = g_gates16 + ((size_t)(b * T_ + s * CH_)) * NG;
    float* op = out + ((size_t)(b * T_ + s * CH_)) * U_;
    float2 c = *(const float2*)(g_carry + (b * S_ + s) * U_ + u);
    for (int t = 0; t < CH_; t++) {
        float2 x = __half22float2(*(const __half2*)(gp + (size_t)t * NG + u));
        float2 f = __half22float2(*(const __half2*)(gp + (size_t)t * NG + U_ + u));
        float2 o = __half22float2(*(const __half2*)(gp + (size_t)t * NG + 2 * U_ + u));
        c.x = fmaf(f.x, c.x - x.x, x.x);
        c.y = fmaf(f.y, c.y - x.y, x.y);
        *(float2*)(op + (size_t)t * U_ + u) = make_float2(o.x * c.x, o.y * c.y);
    }
}

// ---------------------------------------------------------------------------
extern "C" void kernel_launch(void* const* d_in, const int* in_sizes, int n_in,
                              void* d_out, int out_size) {
    const float* in   = (const float*)d_in[0];
    const float* W    = (const float*)d_in[1];
    const float* bias = (const float*)d_in[2];
    float* out = (float*)d_out;

    int na = B_ * TP_ * C_;
    prep_a<<<(na + 255) / 256, 256>>>(in);
    prep_w<<<(K_ * NG + 255) / 256, 256>>>(W);

    cudaFuncSetAttribute(gemm_mma, cudaFuncAttributeMaxDynamicSharedMemorySize, SMEM_TOTAL);
    dim3 gGemm(NG / BN, (B_ * T_) / BM);   // (12, 256)
    gemm_mma<<<gGemm, 256, SMEM_TOTAL>>>(bias);

    dim3 gScan(1, S_, B_);                 // 256 blocks
    scan_partial<<<gScan, 256>>>();
    scan_carry<<<(B_ * U_ + 255) / 256, 256>>>();
    scan_final<<<gScan, 256>>>(out);
}

// round 10
// speedup vs baseline: 5.6817x; 1.2166x over previous
#include <cuda_runtime.h>
#include <cuda_fp16.h>
#include <math.h>
#include <stdint.h>

#define B_  8
#define T_  4096
#define C_  512
#define U_  512
#define NG  1536            // 3*U
#define K_  1024            // 2*C
#define S_  64              // scan chunks
#define CH_ 64              // chunk length (S_*CH_ == T_)
#define TP_ 4097            // padded rows per batch (zero row at t=T)

#define BM  128
#define BN  128
#define BK  64
#define NKK (K_ / BK)       // 16 k-slices
#define NSTAGE 3
#define STAGE_BYTES 32768   // A 16K | W 16K
#define SMEM_TOTAL (NSTAGE * STAGE_BYTES)

// ---- device scratch (allocation-free rule) --------------------------------
__device__ __align__(128) __half g_a16[B_ * TP_ * C_];
__device__ __align__(128) __half g_w16[NG * K_];    // [n][k]
__device__ __align__(128) __half g_gates16[(size_t)B_ * T_ * NG]; // fp16 gates
__device__ float g_cend[B_ * S_ * U_];
__device__ float g_fprod[B_ * S_ * U_];

// ---------------------------------------------------------------------------
__device__ __forceinline__ uint32_t smem_u32(const void* p) {
    uint32_t a;
    asm("{ .reg .u64 t; cvta.to.shared.u64 t, %1; cvt.u32.u64 %0, t; }" : "=r"(a) : "l"(p));
    return a;
}
__device__ __forceinline__ void cp16(uint32_t saddr, const void* gaddr) {
    asm volatile("cp.async.cg.shared.global [%0], [%1], 16;" :: "r"(saddr), "l"(gaddr));
}
__device__ __forceinline__ void cp_commit() {
    asm volatile("cp.async.commit_group;" ::: "memory");
}
__device__ __forceinline__ void cp_wait1() {
    asm volatile("cp.async.wait_group 1;" ::: "memory");
}
__device__ __forceinline__ void ldm_x4(uint32_t* r, uint32_t addr) {
    asm volatile("ldmatrix.sync.aligned.m8n8.x4.shared.b16 {%0,%1,%2,%3}, [%4];"
                 : "=r"(r[0]), "=r"(r[1]), "=r"(r[2]), "=r"(r[3]) : "r"(addr));
}
__device__ __forceinline__ void mma_f16(float* d, const uint32_t* a, uint32_t b0, uint32_t b1) {
    asm volatile(
        "mma.sync.aligned.m16n8k16.row.col.f32.f16.f16.f32 "
        "{%0,%1,%2,%3}, {%4,%5,%6,%7}, {%8,%9}, {%0,%1,%2,%3};"
        : "+f"(d[0]), "+f"(d[1]), "+f"(d[2]), "+f"(d[3])
        : "r"(a[0]), "r"(a[1]), "r"(a[2]), "r"(a[3]), "r"(b0), "r"(b1));
}

// ---------------------------------------------------------------------------
// Prep
// ---------------------------------------------------------------------------
__global__ void prep_a(const float* __restrict__ in) {
    int idx = blockIdx.x * blockDim.x + threadIdx.x;
    if (idx >= B_ * TP_ * C_) return;
    int c = idx & (C_ - 1);
    int r = idx >> 9;
    int b = r / TP_;
    int t = r - b * TP_;
    float v = (t < T_) ? in[((size_t)(b * T_ + t)) * C_ + c] : 0.0f;
    g_a16[idx] = __float2half_rn(v);
}

__global__ void prep_w(const float* __restrict__ W) {
    int idx = blockIdx.x * blockDim.x + threadIdx.x;   // over K_*NG
    if (idx >= K_ * NG) return;
    int k = idx / NG;
    int n = idx - k * NG;
    g_w16[(size_t)n * K_ + k] = __float2half_rn(W[idx]);
}

// ---------------------------------------------------------------------------
// HMMA GEMM, single-product fp16, BK=64, 2 CTAs/SM.
// SMEM tile rows are 128B (full SW128): off = row*128 + ((ch ^ (row&7))<<4)
// grid (NG/BN=12, (B_*T_)/BM=256), 256 threads (8 warps, 2(M) x 4(N))
// ---------------------------------------------------------------------------
__global__ void __launch_bounds__(256, 2) gemm_mma(const float* __restrict__ bias) {
    extern __shared__ char smem[];
    const uint32_t sb = smem_u32(smem);
    const int tid  = threadIdx.x;
    const int wid  = tid >> 5;
    const int lane = tid & 31;

    const int bn  = blockIdx.x, bm = blockIdx.y;
    const int gm0 = bm * BM;
    const int b   = gm0 >> 12;
    const int t0  = gm0 & (T_ - 1);
    const int row0 = b * TP_ + t0;     // padded-row base; window overrun lands in pad row
    const int n0  = bn * BN;

    // per-thread static load coords: 4 (row, chunk) pairs cover 128 rows x 8 chunks
    int ldr[4], ldc[4];
    uint32_t ldo[4];
    const __half* pa[4];
    const __half* pw[4];
#pragma unroll
    for (int j = 0; j < 4; j++) {
        int tt = tid + j * 256;
        ldr[j] = tt >> 3;
        ldc[j] = tt & 7;
        ldo[j] = ldr[j] * 128 + ((ldc[j] ^ (ldr[j] & 7)) << 4);
        pa[j] = g_a16 + (size_t)(row0 + ldr[j]) * C_ + ldc[j] * 8;
        pw[j] = g_w16 + (size_t)(n0 + ldr[j]) * K_ + ldc[j] * 8;
    }

    auto issue = [&](int kk) {
        const uint32_t st = sb + (kk % NSTAGE) * STAGE_BYTES;
        const int kb = kk * BK;
#pragma unroll
        for (int j = 0; j < 4; j++) {
            cp16(st + ldo[j],          pa[j] + kb);
            cp16(st + 16384 + ldo[j],  pw[j] + kb);
        }
    };

    // Warp tile: 64(M) x 32(N)
    const int wm0 = (wid >> 2) * 64;
    const int wn0 = (wid & 3) * 32;

    float acc[4][4][4];
#pragma unroll
    for (int i = 0; i < 4; i++)
#pragma unroll
        for (int j = 0; j < 4; j++)
#pragma unroll
            for (int q = 0; q < 4; q++) acc[i][j][q] = 0.0f;

    issue(0); cp_commit();
    issue(1); cp_commit();

    for (int kk = 0; kk < NKK; kk++) {
        cp_wait1();
        __syncthreads();
        if (kk + 2 < NKK) issue(kk + 2);
        cp_commit();                      // uniform group count

        const uint32_t st = sb + (kk % NSTAGE) * STAGE_BYTES;
        const uint32_t As = st, Ws = st + 16384;

#pragma unroll
        for (int ks = 0; ks < 4; ks++) {
            const int ch = ks * 2 + (lane >> 4);
            uint32_t a[4][4], w[2][4];
#pragma unroll
            for (int mt = 0; mt < 4; mt++) {
                int row = wm0 + mt * 16 + (lane & 15);
                uint32_t off = row * 128 + ((ch ^ (row & 7)) << 4);
                ldm_x4(a[mt], As + off);
            }
#pragma unroll
            for (int bt = 0; bt < 2; bt++) {
                int row = wn0 + bt * 16 + (lane & 15);
                uint32_t off = row * 128 + ((ch ^ (row & 7)) << 4);
                ldm_x4(w[bt], Ws + off);
            }
#pragma unroll
            for (int mt = 0; mt < 4; mt++)
#pragma unroll
                for (int nt = 0; nt < 4; nt++)
                    mma_f16(acc[mt][nt], a[mt], w[nt >> 1][nt & 1], w[nt >> 1][2 + (nt & 1)]);
        }
    }

    // Epilogue: bias + activation + fp16 pack (uniform per CTA: n0 < U_ => tanh)
    const bool is_tanh = (n0 < U_);
    const int grow = lane >> 2;
    const int gcol = (lane & 3) * 2;
#pragma unroll
    for (int mt = 0; mt < 4; mt++) {
#pragma unroll
        for (int nt = 0; nt < 4; nt++) {
            int n = n0 + wn0 + nt * 8 + gcol;
            float b0 = __ldg(bias + n);
            float b1 = __ldg(bias + n + 1);
#pragma unroll
            for (int h = 0; h < 2; h++) {
                int m = gm0 + wm0 + mt * 16 + grow + h * 8;
                float v0 = acc[mt][nt][2 * h]     + b0;
                float v1 = acc[mt][nt][2 * h + 1] + b1;
                if (is_tanh) {
                    float e0 = __expf(2.0f * v0), e1 = __expf(2.0f * v1);
                    v0 = 1.0f - 2.0f / (e0 + 1.0f);
                    v1 = 1.0f - 2.0f / (e1 + 1.0f);
                } else {
                    v0 = 1.0f / (1.0f + __expf(-v0));
                    v1 = 1.0f / (1.0f + __expf(-v1));
                }
                *(__half2*)(g_gates16 + (size_t)m * NG + n) = __floats2half2_rn(v0, v1);
            }
        }
    }
}

// ---------------------------------------------------------------------------
// Scan passes: fp16 gates, fp32 math. grid (1, S_, B_) = 512 blocks.
// ---------------------------------------------------------------------------
__global__ void __launch_bounds__(256) scan_partial() {
    int u = threadIdx.x * 2;
    int s = blockIdx.y;
    int b = blockIdx.z;
    const __half* gp = g_gates16 + ((size_t)(b * T_ + s * CH_)) * NG;
    float2 c = make_float2(0.f, 0.f), F = make_float2(1.f, 1.f);
    for (int t = 0; t < CH_; t++) {
        float2 x = __half22float2(*(const __half2*)(gp + (size_t)t * NG + u));
        float2 f = __half22float2(*(const __half2*)(gp + (size_t)t * NG + U_ + u));
        c.x = fmaf(f.x, c.x - x.x, x.x);
        c.y = fmaf(f.y, c.y - x.y, x.y);
        F.x *= f.x; F.y *= f.y;
    }
    int off = (b * S_ + s) * U_ + u;
    *(float2*)(g_cend  + off) = c;
    *(float2*)(g_fprod + off) = F;
}

// scan_final computes its own carry prefix from the chunk summaries
// (<= S_-1 dependent FMAs over L2-resident data), then replays its chunk.
__global__ void __launch_bounds__(256) scan_final(float* __restrict__ out) {
    int u = threadIdx.x * 2;
    int s = blockIdx.y;
    int b = blockIdx.z;

    float2 c = make_float2(0.f, 0.f);
    for (int sp = 0; sp < s; sp++) {
        int off = (b * S_ + sp) * U_ + u;
        float2 F = *(const float2*)(g_fprod + off);
        float2 E = *(const float2*)(g_cend  + off);
        c.x = fmaf(F.x, c.x, E.x);
        c.y = fmaf(F.y, c.y, E.y);
    }

    const __half* gp = g_gates16 + ((size_t)(b * T_ + s * CH_)) * NG;
    float* op = out + ((size_t)(b * T_ + s * CH_)) * U_;
    for (int t = 0; t < CH_; t++) {
        float2 x = __half22float2(*(const __half2*)(gp + (size_t)t * NG + u));
        float2 f = __half22float2(*(const __half2*)(gp + (size_t)t * NG + U_ + u));
        float2 o = __half22float2(*(const __half2*)(gp + (size_t)t * NG + 2 * U_ + u));
        c.x = fmaf(f.x, c.x - x.x, x.x);
        c.y = fmaf(f.y, c.y - x.y, x.y);
        *(float2*)(op + (size_t)t * U_ + u) = make_float2(o.x * c.x, o.y * c.y);
    }
}

// ---------------------------------------------------------------------------
extern "C" void kernel_launch(void* const* d_in, const int* in_sizes, int n_in,
                              void* d_out, int out_size) {
    const float* in   = (const float*)d_in[0];
    const float* W    = (const float*)d_in[1];
    const float* bias = (const float*)d_in[2];
    float* out = (float*)d_out;

    int na = B_ * TP_ * C_;
    prep_a<<<(na + 255) / 256, 256>>>(in);
    prep_w<<<(K_ * NG + 255) / 256, 256>>>(W);

    cudaFuncSetAttribute(gemm_mma, cudaFuncAttributeMaxDynamicSharedMemorySize, SMEM_TOTAL);
    dim3 gGemm(NG / BN, (B_ * T_) / BM);   // (12, 256)
    gemm_mma<<<gGemm, 256, SMEM_TOTAL>>>(bias);

    dim3 gScan(1, S_, B_);                 // 512 blocks
    scan_partial<<<gScan, 256>>>();
    scan_final<<<gScan, 256>>>(out);
}

// round 11
// speedup vs baseline: 6.2234x; 1.0953x over previous
#include <cuda_runtime.h>
#include <cuda_fp16.h>
#include <math.h>
#include <stdint.h>

#define B_  8
#define T_  4096
#define C_  512
#define U_  512
#define NG  1536            // 3*U
#define K_  1024            // 2*C
#define S_  64              // scan chunks
#define CH_ 64              // chunk length (S_*CH_ == T_)
#define TP_ 4097            // padded rows per batch (zero row at t=T)

#define BM  128
#define BN  128
#define BK  64
#define NKK (K_ / BK)       // 16 k-slices
#define NSTAGE 3
#define STAGE_BYTES 32768   // A 16K | W 16K
#define SMEM_TOTAL (NSTAGE * STAGE_BYTES)

// ---- device scratch (allocation-free rule) --------------------------------
__device__ __align__(128) __half g_a16[B_ * TP_ * C_];
__device__ __align__(128) __half g_w16[NG * K_];    // [n][k]
__device__ __align__(128) __half g_gates16[(size_t)B_ * T_ * NG]; // fp16 gates
__device__ float g_cend[B_ * S_ * U_];
__device__ float g_fprod[B_ * S_ * U_];

// ---------------------------------------------------------------------------
__device__ __forceinline__ uint32_t smem_u32(const void* p) {
    uint32_t a;
    asm("{ .reg .u64 t; cvta.to.shared.u64 t, %1; cvt.u32.u64 %0, t; }" : "=r"(a) : "l"(p));
    return a;
}
__device__ __forceinline__ void cp16(uint32_t saddr, const void* gaddr) {
    asm volatile("cp.async.cg.shared.global [%0], [%1], 16;" :: "r"(saddr), "l"(gaddr));
}
__device__ __forceinline__ void cp_commit() {
    asm volatile("cp.async.commit_group;" ::: "memory");
}
__device__ __forceinline__ void cp_wait1() {
    asm volatile("cp.async.wait_group 1;" ::: "memory");
}
__device__ __forceinline__ void ldm_x4(uint32_t* r, uint32_t addr) {
    asm volatile("ldmatrix.sync.aligned.m8n8.x4.shared.b16 {%0,%1,%2,%3}, [%4];"
                 : "=r"(r[0]), "=r"(r[1]), "=r"(r[2]), "=r"(r[3]) : "r"(addr));
}
__device__ __forceinline__ void mma_f16(float* d, const uint32_t* a, uint32_t b0, uint32_t b1) {
    asm volatile(
        "mma.sync.aligned.m16n8k16.row.col.f32.f16.f16.f32 "
        "{%0,%1,%2,%3}, {%4,%5,%6,%7}, {%8,%9}, {%0,%1,%2,%3};"
        : "+f"(d[0]), "+f"(d[1]), "+f"(d[2]), "+f"(d[3])
        : "r"(a[0]), "r"(a[1]), "r"(a[2]), "r"(a[3]), "r"(b0), "r"(b1));
}

// ---------------------------------------------------------------------------
// Prep A: fp32 -> fp16, vectorized x4 (float4 loads, half2 stores)
// ---------------------------------------------------------------------------
__global__ void prep_a(const float* __restrict__ in) {
    int idx = blockIdx.x * blockDim.x + threadIdx.x;     // over (B_*TP_*C_)/4
    if (idx >= (B_ * TP_ * C_) / 4) return;
    int c4 = idx & (C_ / 4 - 1);
    int r  = idx >> 7;
    int b  = r / TP_;
    int t  = r - b * TP_;
    __half2 h0, h1;
    if (t < T_) {
        float4 v = *(const float4*)(in + ((size_t)(b * T_ + t)) * C_ + c4 * 4);
        h0 = __floats2half2_rn(v.x, v.y);
        h1 = __floats2half2_rn(v.z, v.w);
    } else {
        h0 = __floats2half2_rn(0.f, 0.f);
        h1 = h0;
    }
    *(__half2*)(g_a16 + (size_t)idx * 4)     = h0;
    *(__half2*)(g_a16 + (size_t)idx * 4 + 2) = h1;
}

// ---------------------------------------------------------------------------
// Prep W: [k][n] fp32 -> [n][k] fp16, smem 32x32 tile transpose (coalesced both ways)
// grid (NG/32=48, K_/32=32), 256 threads (32x8)
// ---------------------------------------------------------------------------
__global__ void __launch_bounds__(256) prep_w(const float* __restrict__ W) {
    __shared__ float tile[32][33];
    const int n0 = blockIdx.x * 32;
    const int k0 = blockIdx.y * 32;
    const int tx = threadIdx.x & 31;
    const int ty = threadIdx.x >> 5;      // 0..7
#pragma unroll
    for (int j = 0; j < 4; j++) {
        int k = ty + j * 8;
        tile[k][tx] = W[(size_t)(k0 + k) * NG + n0 + tx];   // coalesced along n
    }
    __syncthreads();
#pragma unroll
    for (int j = 0; j < 4; j++) {
        int n = ty + j * 8;
        g_w16[(size_t)(n0 + n) * K_ + k0 + tx] = __float2half_rn(tile[tx][n]); // coalesced along k
    }
}

// ---------------------------------------------------------------------------
// HMMA GEMM, single-product fp16, BK=64, 2 CTAs/SM. (unchanged from R10)
// ---------------------------------------------------------------------------
__global__ void __launch_bounds__(256, 2) gemm_mma(const float* __restrict__ bias) {
    extern __shared__ char smem[];
    const uint32_t sb = smem_u32(smem);
    const int tid  = threadIdx.x;
    const int wid  = tid >> 5;
    const int lane = tid & 31;

    const int bn  = blockIdx.x, bm = blockIdx.y;
    const int gm0 = bm * BM;
    const int b   = gm0 >> 12;
    const int t0  = gm0 & (T_ - 1);
    const int row0 = b * TP_ + t0;
    const int n0  = bn * BN;

    int ldr[4], ldc[4];
    uint32_t ldo[4];
    const __half* pa[4];
    const __half* pw[4];
#pragma unroll
    for (int j = 0; j < 4; j++) {
        int tt = tid + j * 256;
        ldr[j] = tt >> 3;
        ldc[j] = tt & 7;
        ldo[j] = ldr[j] * 128 + ((ldc[j] ^ (ldr[j] & 7)) << 4);
        pa[j] = g_a16 + (size_t)(row0 + ldr[j]) * C_ + ldc[j] * 8;
        pw[j] = g_w16 + (size_t)(n0 + ldr[j]) * K_ + ldc[j] * 8;
    }

    auto issue = [&](int kk) {
        const uint32_t st = sb + (kk % NSTAGE) * STAGE_BYTES;
        const int kb = kk * BK;
#pragma unroll
        for (int j = 0; j < 4; j++) {
            cp16(st + ldo[j],          pa[j] + kb);
            cp16(st + 16384 + ldo[j],  pw[j] + kb);
        }
    };

    const int wm0 = (wid >> 2) * 64;
    const int wn0 = (wid & 3) * 32;

    float acc[4][4][4];
#pragma unroll
    for (int i = 0; i < 4; i++)
#pragma unroll
        for (int j = 0; j < 4; j++)
#pragma unroll
            for (int q = 0; q < 4; q++) acc[i][j][q] = 0.0f;

    issue(0); cp_commit();
    issue(1); cp_commit();

    for (int kk = 0; kk < NKK; kk++) {
        cp_wait1();
        __syncthreads();
        if (kk + 2 < NKK) issue(kk + 2);
        cp_commit();

        const uint32_t st = sb + (kk % NSTAGE) * STAGE_BYTES;
        const uint32_t As = st, Ws = st + 16384;

#pragma unroll
        for (int ks = 0; ks < 4; ks++) {
            const int ch = ks * 2 + (lane >> 4);
            uint32_t a[4][4], w[2][4];
#pragma unroll
            for (int mt = 0; mt < 4; mt++) {
                int row = wm0 + mt * 16 + (lane & 15);
                uint32_t off = row * 128 + ((ch ^ (row & 7)) << 4);
                ldm_x4(a[mt], As + off);
            }
#pragma unroll
            for (int bt = 0; bt < 2; bt++) {
                int row = wn0 + bt * 16 + (lane & 15);
                uint32_t off = row * 128 + ((ch ^ (row & 7)) << 4);
                ldm_x4(w[bt], Ws + off);
            }
#pragma unroll
            for (int mt = 0; mt < 4; mt++)
#pragma unroll
                for (int nt = 0; nt < 4; nt++)
                    mma_f16(acc[mt][nt], a[mt], w[nt >> 1][nt & 1], w[nt >> 1][2 + (nt & 1)]);
        }
    }

    const bool is_tanh = (n0 < U_);
    const int grow = lane >> 2;
    const int gcol = (lane & 3) * 2;
#pragma unroll
    for (int mt = 0; mt < 4; mt++) {
#pragma unroll
        for (int nt = 0; nt < 4; nt++) {
            int n = n0 + wn0 + nt * 8 + gcol;
            float b0 = __ldg(bias + n);
            float b1 = __ldg(bias + n + 1);
#pragma unroll
            for (int h = 0; h < 2; h++) {
                int m = gm0 + wm0 + mt * 16 + grow + h * 8;
                float v0 = acc[mt][nt][2 * h]     + b0;
                float v1 = acc[mt][nt][2 * h + 1] + b1;
                if (is_tanh) {
                    float e0 = __expf(2.0f * v0), e1 = __expf(2.0f * v1);
                    v0 = 1.0f - 2.0f / (e0 + 1.0f);
                    v1 = 1.0f - 2.0f / (e1 + 1.0f);
                } else {
                    v0 = 1.0f / (1.0f + __expf(-v0));
                    v1 = 1.0f / (1.0f + __expf(-v1));
                }
                *(__half2*)(g_gates16 + (size_t)m * NG + n) = __floats2half2_rn(v0, v1);
            }
        }
    }
}

// ---------------------------------------------------------------------------
// Scan passes: fp16 gates, fp32 math, unroll-4 for load MLP.
// grid (1, S_, B_) = 512 blocks.
// ---------------------------------------------------------------------------
__global__ void __launch_bounds__(256) scan_partial() {
    int u = threadIdx.x * 2;
    int s = blockIdx.y;
    int b = blockIdx.z;
    const __half* gp = g_gates16 + ((size_t)(b * T_ + s * CH_)) * NG;
    float2 c = make_float2(0.f, 0.f), F = make_float2(1.f, 1.f);
#pragma unroll 4
    for (int t = 0; t < CH_; t++) {
        float2 x = __half22float2(*(const __half2*)(gp + (size_t)t * NG + u));
        float2 f = __half22float2(*(const __half2*)(gp + (size_t)t * NG + U_ + u));
        c.x = fmaf(f.x, c.x - x.x, x.x);
        c.y = fmaf(f.y, c.y - x.y, x.y);
        F.x *= f.x; F.y *= f.y;
    }
    int off = (b * S_ + s) * U_ + u;
    *(float2*)(g_cend  + off) = c;
    *(float2*)(g_fprod + off) = F;
}

__global__ void __launch_bounds__(256) scan_final(float* __restrict__ out) {
    int u = threadIdx.x * 2;
    int s = blockIdx.y;
    int b = blockIdx.z;

    float2 c = make_float2(0.f, 0.f);
#pragma unroll 4
    for (int sp = 0; sp < s; sp++) {
        int off = (b * S_ + sp) * U_ + u;
        float2 F = *(const float2*)(g_fprod + off);
        float2 E = *(const float2*)(g_cend  + off);
        c.x = fmaf(F.x, c.x, E.x);
        c.y = fmaf(F.y, c.y, E.y);
    }

    const __half* gp = g_gates16 + ((size_t)(b * T_ + s * CH_)) * NG;
    float* op = out + ((size_t)(b * T_ + s * CH_)) * U_;
#pragma unroll 4
    for (int t = 0; t < CH_; t++) {
        float2 x = __half22float2(*(const __half2*)(gp + (size_t)t * NG + u));
        float2 f = __half22float2(*(const __half2*)(gp + (size_t)t * NG + U_ + u));
        float2 o = __half22float2(*(const __half2*)(gp + (size_t)t * NG + 2 * U_ + u));
        c.x = fmaf(f.x, c.x - x.x, x.x);
        c.y = fmaf(f.y, c.y - x.y, x.y);
        *(float2*)(op + (size_t)t * U_ + u) = make_float2(o.x * c.x, o.y * c.y);
    }
}

// ---------------------------------------------------------------------------
extern "C" void kernel_launch(void* const* d_in, const int* in_sizes, int n_in,
                              void* d_out, int out_size) {
    const float* in   = (const float*)d_in[0];
    const float* W    = (const float*)d_in[1];
    const float* bias = (const float*)d_in[2];
    float* out = (float*)d_out;

    int na4 = (B_ * TP_ * C_) / 4;
    prep_a<<<(na4 + 255) / 256, 256>>>(in);
    dim3 gW(NG / 32, K_ / 32);             // (48, 32)
    prep_w<<<gW, 256>>>(W);

    cudaFuncSetAttribute(gemm_mma, cudaFuncAttributeMaxDynamicSharedMemorySize, SMEM_TOTAL);
    dim3 gGemm(NG / BN, (B_ * T_) / BM);   // (12, 256)
    gemm_mma<<<gGemm, 256, SMEM_TOTAL>>>(bias);

    dim3 gScan(1, S_, B_);                 // 512 blocks
    scan_partial<<<gScan, 256>>>();
    scan_final<<<gScan, 256>>>(out);
}